// round 8
// baseline (speedup 1.0000x reference)
#include <cuda_runtime.h>
#include <cstdint>
#include <cstddef>

#define B_ 4
#define L_ 2048
#define D_ 1024
#define H_ 16
#define HD_ 64
#define NX (B_*L_*D_)

// Scratch (allocation-free rule: __device__ globals)
__device__ float g_qh[NX];          // [b,h,l,hd]  hd pair-permuted, tf32, pre-scaled 0.125
__device__ float g_kh[NX];          // hd pair-permuted, tf32
__device__ float g_vh[NX];          // natural hd, tf32
__device__ float g_ao[NX];          // [b,l,d], d pair-permuted, tf32
__device__ float g_xr[3][NX];       // k-dim pair-permuted, tf32 q,k,v
__device__ float g_wr[4][D_*D_];    // in-dim pair-permuted, tf32 Wq,Wk,Wv,Wo

// ---------------- helpers ----------------
__device__ __forceinline__ uint32_t s2u(const void* p) {
    uint32_t a;
    asm("{ .reg .u64 t; cvta.to.shared.u64 t, %1; cvt.u32.u64 %0, t; }" : "=r"(a) : "l"(p));
    return a;
}
__device__ __forceinline__ uint32_t f2tf32(float f) {
    uint32_t u;
    asm("cvt.rna.tf32.f32 %0, %1;" : "=r"(u) : "f"(f));
    return u;
}
__device__ __forceinline__ float rtf(float f) { return __uint_as_float(f2tf32(f)); }
__device__ __forceinline__ void mma_tf32_16x8x8(float* c, const uint32_t* a, const uint32_t* b) {
    asm volatile(
        "mma.sync.aligned.m16n8k8.row.col.f32.tf32.tf32.f32 "
        "{%0,%1,%2,%3}, {%4,%5,%6,%7}, {%8,%9}, {%0,%1,%2,%3};"
        : "+f"(c[0]), "+f"(c[1]), "+f"(c[2]), "+f"(c[3])
        : "r"(a[0]), "r"(a[1]), "r"(a[2]), "r"(a[3]), "r"(b[0]), "r"(b[1]));
}

// ---------------- tf32 round + pair-permute passes ----------------
__global__ void __launch_bounds__(256) round_x(const float* __restrict__ q,
        const float* __restrict__ k, const float* __restrict__ v)
{
    const int z = blockIdx.y;
    const float* src = (z == 0) ? q : (z == 1) ? k : v;
    float* dst = g_xr[z];
    int i = (blockIdx.x * 256 + threadIdx.x) * 8;
    float4 in0 = *(const float4*)(src + i);
    float4 in1 = *(const float4*)(src + i + 4);
    float4 o0 = make_float4(rtf(in0.x), rtf(in1.x), rtf(in0.y), rtf(in1.y));
    float4 o1 = make_float4(rtf(in0.z), rtf(in1.z), rtf(in0.w), rtf(in1.w));
    *(float4*)(dst + i) = o0;
    *(float4*)(dst + i + 4) = o1;
}
__global__ void __launch_bounds__(256) round_w(const float* __restrict__ wq,
        const float* __restrict__ wk, const float* __restrict__ wv,
        const float* __restrict__ wo)
{
    const int z = blockIdx.y;
    const float* src = (z == 0) ? wq : (z == 1) ? wk : (z == 2) ? wv : wo;
    float* dst = g_wr[z];
    int i = (blockIdx.x * 256 + threadIdx.x) * 8;
    float4 in0 = *(const float4*)(src + i);
    float4 in1 = *(const float4*)(src + i + 4);
    float4 o0 = make_float4(rtf(in0.x), rtf(in1.x), rtf(in0.y), rtf(in1.y));
    float4 o1 = make_float4(rtf(in0.z), rtf(in1.z), rtf(in0.w), rtf(in1.w));
    *(float4*)(dst + i) = o0;
    *(float4*)(dst + i + 4) = o1;
}

#define APITCH 40
#define ASZ  (128 * APITCH)
#define GEMM_SMEM (4 * ASZ * 4)
#define NIT  (D_ / 32)

// ---------------- shared GEMM core (tf32 mma.sync, 128x128x32, 8 warps) ----------------
struct GemmAcc { float a[2][8][4]; };

__device__ __forceinline__ void gemm_core(const float* __restrict__ Xa,
                                          const float* __restrict__ Wb,
                                          float* sm, int tid, GemmAcc& acc)
{
    const int wid = tid >> 5, lane = tid & 31;
    const int wm = wid >> 1, wn = wid & 1;
    const int g = lane >> 2, t4 = lane & 3;

    #pragma unroll
    for (int am = 0; am < 2; am++)
        #pragma unroll
        for (int na = 0; na < 8; na++)
            #pragma unroll
            for (int q = 0; q < 4; q++) acc.a[am][na][q] = 0.f;

    auto load_stage = [&](int ck, int s) {
        float* As = sm + s * ASZ;
        float* Bs = sm + 2 * ASZ + s * ASZ;
        #pragma unroll
        for (int i = 0; i < 4; i++) {
            int id = tid + i * 256;
            int r = id >> 3, u = id & 7;
            uint32_t da = s2u(As + r * APITCH + u * 4);
            uint32_t db = s2u(Bs + r * APITCH + u * 4);
            asm volatile("cp.async.cg.shared.global [%0], [%1], 16;"
                         :: "r"(da), "l"(Xa + (size_t)r * D_ + ck * 32 + u * 4));
            asm volatile("cp.async.cg.shared.global [%0], [%1], 16;"
                         :: "r"(db), "l"(Wb + (size_t)r * D_ + ck * 32 + u * 4));
        }
        asm volatile("cp.async.commit_group;");
    };

    load_stage(0, 0);

    for (int it = 0; it < NIT; it++) {
        if (it + 1 < NIT) {
            load_stage(it + 1, (it + 1) & 1);
            asm volatile("cp.async.wait_group 1;");
        } else {
            asm volatile("cp.async.wait_group 0;");
        }
        __syncthreads();

        const float* As = sm + (it & 1) * ASZ;
        const float* Bs = sm + 2 * ASZ + (it & 1) * ASZ;

        #pragma unroll
        for (int kk = 0; kk < 4; kk++) {
            const int c2 = kk * 8 + 2 * t4;
            uint32_t a[2][4];
            #pragma unroll
            for (int am = 0; am < 2; am++) {
                int r = wm * 32 + am * 16 + g;
                float2 p0 = *(const float2*)(As + r * APITCH + c2);
                float2 p1 = *(const float2*)(As + (r + 8) * APITCH + c2);
                a[am][0] = __float_as_uint(p0.x);
                a[am][1] = __float_as_uint(p1.x);
                a[am][2] = __float_as_uint(p0.y);
                a[am][3] = __float_as_uint(p1.y);
            }
            uint32_t b[8][2];
            #pragma unroll
            for (int na = 0; na < 8; na++) {
                int n = wn * 64 + na * 8 + g;
                float2 pb = *(const float2*)(Bs + n * APITCH + c2);
                b[na][0] = __float_as_uint(pb.x);
                b[na][1] = __float_as_uint(pb.y);
            }
            #pragma unroll
            for (int am = 0; am < 2; am++)
                #pragma unroll
                for (int na = 0; na < 8; na++)
                    mma_tf32_16x8x8(acc.a[am][na], a[am], b[na]);
        }
        __syncthreads();
    }
}

// Merged Q/K/V projection: grid (8, 64, 3).
__global__ void __launch_bounds__(256, 2)
gemm_proj3(float* __restrict__ qh, float* __restrict__ kh, float* __restrict__ vh)
{
    extern __shared__ float sm[];
    const int tid = threadIdx.x;
    const int z = blockIdx.z;
    const int m0 = blockIdx.y * 128, n0 = blockIdx.x * 128;

    const float* X = g_xr[z];
    const float* W = g_wr[z];
    float* Y = (z == 0) ? qh : (z == 1) ? kh : vh;
    const float scale = (z == 0) ? 0.125f : 1.0f;

    GemmAcc acc;
    gemm_core(X + (size_t)m0 * D_, W + (size_t)n0 * D_, sm, tid, acc);

    const int wid = tid >> 5, lane = tid & 31;
    const int wm = wid >> 1, wn = wid & 1;
    const int g = lane >> 2, t4 = lane & 3;
    const int pos0 = (t4 & 1) * 4 + (t4 >> 1);   // P(2*t4) within 8-group

    #pragma unroll
    for (int am = 0; am < 2; am++) {
        int r = m0 + wm * 32 + am * 16 + g;
        int b = r >> 11, l = r & 2047;
        #pragma unroll
        for (int na = 0; na < 8; na++) {
            int n = n0 + wn * 64 + na * 8 + 2 * t4;
            int h = n >> 6, hd = n & 63;
            int hdg = hd & ~7;
            int i0 = (z == 2) ? hd : (hdg + pos0);
            int i1 = (z == 2) ? (hd + 1) : (hdg + pos0 + 2);
            float* p0 = Y + (((size_t)b * H_ + h) * L_ + l) * HD_;
            p0[i0] = rtf(acc.a[am][na][0]) * scale;
            p0[i1] = rtf(acc.a[am][na][1]) * scale;
            float* p1 = Y + (((size_t)b * H_ + h) * L_ + (l + 8)) * HD_;
            p1[i0] = rtf(acc.a[am][na][2]) * scale;
            p1[i1] = rtf(acc.a[am][na][3]) * scale;
        }
    }
}

// Output projection
__global__ void __launch_bounds__(256, 2)
gemm_out(const float* __restrict__ X, float* __restrict__ Y)
{
    extern __shared__ float sm[];
    const int tid = threadIdx.x;
    const int m0 = blockIdx.y * 128, n0 = blockIdx.x * 128;

    GemmAcc acc;
    gemm_core(X + (size_t)m0 * D_, g_wr[3] + (size_t)n0 * D_, sm, tid, acc);

    const int wid = tid >> 5, lane = tid & 31;
    const int wm = wid >> 1, wn = wid & 1;
    const int g = lane >> 2, t4 = lane & 3;

    #pragma unroll
    for (int am = 0; am < 2; am++) {
        int r = m0 + wm * 32 + am * 16 + g;
        #pragma unroll
        for (int na = 0; na < 8; na++) {
            int n = n0 + wn * 64 + na * 8 + 2 * t4;
            float* p0 = Y + (size_t)r * D_ + n;
            p0[0] = acc.a[am][na][0]; p0[1] = acc.a[am][na][1];
            float* p1 = Y + (size_t)(r + 8) * D_ + n;
            p1[0] = acc.a[am][na][2]; p1[1] = acc.a[am][na][3];
        }
    }
}

// ---------------- tf32 mma.sync flash attention (persistent, 8 warps x 16 rows) ----------------
#define QPQ 72
#define QPV 68
#define KSTAGE (64 * QPQ + 64 * QPV)
#define ATTN_SMEM ((128 * QPQ + 2 * KSTAGE) * 4)
#define NBLK 296

__global__ void __launch_bounds__(256, 2) attn_mma(
        const float* __restrict__ qh, const float* __restrict__ kh,
        const float* __restrict__ vh, float* __restrict__ ao)
{
    extern __shared__ float sm[];
    float* Qs = sm;
    float* KV = sm + 128 * QPQ;

    const int tid = threadIdx.x;
    const int wid = tid >> 5, lane = tid & 31;
    const int g = lane >> 2, t4 = lane & 3;
    const int p = blockIdx.x;
    const int pos0 = (t4 & 1) * 4 + (t4 >> 1);

    const int srcA = (lane & ~3) | (t4 >> 1);
    const int srcB = srcA + 2;

    #pragma unroll 1
    for (int round = 0; round < 4; round++) {
        int rank = (round == 0) ? p
                 : (round == 1) ? (591 - p)
                 : (round == 2) ? (592 + p)
                 : (1183 - p);
        if (rank >= 1024) continue;
        const int qt = 15 - (rank >> 6);     // heavy first
        const int bh = rank & 63;
        const int q0 = qt * 128;

        const float* Qb = qh + ((size_t)bh * L_ + q0) * HD_;
        const float* Kb = kh + (size_t)bh * L_ * HD_;
        const float* Vb = vh + (size_t)bh * L_ * HD_;

        __syncthreads();   // smem free from previous tile

        #pragma unroll
        for (int i = 0; i < 8; i++) {
            int e = tid + i * 256;
            int r = e >> 4, c4 = (e & 15) * 4;
            *(float4*)(Qs + r * QPQ + c4) = *(const float4*)(Qb + (size_t)r * 64 + c4);
        }

        auto ldkv = [&](int kt, int st) {
            float* Ks = KV + st * KSTAGE;
            float* Vs = Ks + 64 * QPQ;
            const float* kg = Kb + (size_t)kt * 64 * 64;
            const float* vg = Vb + (size_t)kt * 64 * 64;
            #pragma unroll
            for (int i = 0; i < 4; i++) {
                int e = tid + i * 256;
                int r = e >> 4, c = (e & 15) * 4;
                asm volatile("cp.async.cg.shared.global [%0], [%1], 16;"
                             :: "r"(s2u(Ks + r * QPQ + c)), "l"(kg + (size_t)r * 64 + c));
                asm volatile("cp.async.cg.shared.global [%0], [%1], 16;"
                             :: "r"(s2u(Vs + r * QPV + c)), "l"(vg + (size_t)r * 64 + c));
            }
            asm volatile("cp.async.commit_group;");
        };

        float mrun[2], lrun[2], O[8][4];
        #pragma unroll
        for (int i = 0; i < 2; i++) { mrun[i] = -1e30f; lrun[i] = 0.f; }
        #pragma unroll
        for (int nt = 0; nt < 8; nt++)
            #pragma unroll
            for (int e = 0; e < 4; e++) O[nt][e] = 0.f;

        const int ntiles = 2 * qt + 2;
        ldkv(0, 0);

        for (int kt = 0; kt < ntiles; kt++) {
            asm volatile("cp.async.wait_group 0;");
            __syncthreads();
            if (kt + 1 < ntiles) ldkv(kt + 1, (kt + 1) & 1);
            const float* Ks = KV + (kt & 1) * KSTAGE;
            const float* Vs = Ks + 64 * QPQ;

            float S[8][4];
            #pragma unroll
            for (int nt = 0; nt < 8; nt++)
                #pragma unroll
                for (int e = 0; e < 4; e++) S[nt][e] = 0.f;

            #pragma unroll
            for (int kc = 0; kc < 8; kc++) {
                const int c2 = kc * 8 + 2 * t4;
                uint32_t af[4];
                {
                    int r = wid * 16 + g;
                    float2 q0f = *(const float2*)(Qs + r * QPQ + c2);
                    float2 q1f = *(const float2*)(Qs + (r + 8) * QPQ + c2);
                    af[0] = __float_as_uint(q0f.x);
                    af[1] = __float_as_uint(q1f.x);
                    af[2] = __float_as_uint(q0f.y);
                    af[3] = __float_as_uint(q1f.y);
                }
                #pragma unroll
                for (int nt = 0; nt < 8; nt++) {
                    float2 kf = *(const float2*)(Ks + (nt * 8 + g) * QPQ + c2);
                    uint32_t bf[2];
                    bf[0] = __float_as_uint(kf.x);
                    bf[1] = __float_as_uint(kf.y);
                    mma_tf32_16x8x8(S[nt], af, bf);
                }
            }

            const bool maskt = (kt >= ntiles - 2);
            #pragma unroll
            for (int rr = 0; rr < 2; rr++) {
                const int rowg = q0 + wid * 16 + rr * 8 + g;
                float mloc = -1e30f;
                #pragma unroll
                for (int nt = 0; nt < 8; nt++)
                    #pragma unroll
                    for (int e = 0; e < 2; e++) {
                        float vv = S[nt][rr * 2 + e];
                        if (maskt && (kt * 64 + nt * 8 + 2 * t4 + e) > rowg) vv = -1e30f;
                        S[nt][rr * 2 + e] = vv;
                        mloc = fmaxf(mloc, vv);
                    }
                mloc = fmaxf(mloc, __shfl_xor_sync(0xffffffffu, mloc, 1));
                mloc = fmaxf(mloc, __shfl_xor_sync(0xffffffffu, mloc, 2));
                float mnew = fmaxf(mrun[rr], mloc);
                float corr = __expf(mrun[rr] - mnew);
                float sum = 0.f;
                #pragma unroll
                for (int nt = 0; nt < 8; nt++)
                    #pragma unroll
                    for (int e = 0; e < 2; e++) {
                        float pe = __expf(S[nt][rr * 2 + e] - mnew);
                        S[nt][rr * 2 + e] = pe;
                        sum += pe;
                    }
                sum += __shfl_xor_sync(0xffffffffu, sum, 1);
                sum += __shfl_xor_sync(0xffffffffu, sum, 2);
                lrun[rr] = lrun[rr] * corr + sum;
                mrun[rr] = mnew;
                #pragma unroll
                for (int nt = 0; nt < 8; nt++)
                    #pragma unroll
                    for (int e = 0; e < 2; e++)
                        O[nt][rr * 2 + e] *= corr;
            }

            #pragma unroll
            for (int nt = 0; nt < 8; nt++)
                #pragma unroll
                for (int e = 0; e < 4; e++)
                    S[nt][e] = __uint_as_float(f2tf32(S[nt][e]));

            #pragma unroll
            for (int kc = 0; kc < 8; kc++) {
                uint32_t a[4];
                {
                    float v0 = __shfl_sync(0xffffffffu, S[kc][0], srcA);
                    float v1 = __shfl_sync(0xffffffffu, S[kc][1], srcA);
                    float v2 = __shfl_sync(0xffffffffu, S[kc][2], srcA);
                    float v3 = __shfl_sync(0xffffffffu, S[kc][3], srcA);
                    float w0 = __shfl_sync(0xffffffffu, S[kc][0], srcB);
                    float w1 = __shfl_sync(0xffffffffu, S[kc][1], srcB);
                    float w2 = __shfl_sync(0xffffffffu, S[kc][2], srcB);
                    float w3 = __shfl_sync(0xffffffffu, S[kc][3], srcB);
                    a[0] = __float_as_uint((t4 & 1) ? v1 : v0);
                    a[1] = __float_as_uint((t4 & 1) ? v3 : v2);
                    a[2] = __float_as_uint((t4 & 1) ? w1 : w0);
                    a[3] = __float_as_uint((t4 & 1) ? w3 : w2);
                }
                #pragma unroll
                for (int nt = 0; nt < 8; nt++) {
                    uint32_t bf[2];
                    bf[0] = __float_as_uint(Vs[(kc * 8 + t4) * QPV + nt * 8 + g]);
                    bf[1] = __float_as_uint(Vs[(kc * 8 + t4 + 4) * QPV + nt * 8 + g]);
                    mma_tf32_16x8x8(O[nt], a, bf);
                }
            }
        }

        // ---- epilogue: normalize + tf32-round + write pair-permuted [b, l, d] ----
        const int b = bh >> 4, h = bh & 15;
        #pragma unroll
        for (int rr = 0; rr < 2; rr++) {
            float inv = 1.f / lrun[rr];
            int row = q0 + wid * 16 + rr * 8 + g;
            float* op = ao + ((size_t)b * L_ + row) * D_ + h * 64;
            #pragma unroll
            for (int nt = 0; nt < 8; nt++) {
                op[nt * 8 + pos0]     = rtf(O[nt][rr * 2] * inv);
                op[nt * 8 + pos0 + 2] = rtf(O[nt][rr * 2 + 1] * inv);
            }
        }
    }
}

// ---------------- launch ----------------
extern "C" void kernel_launch(void* const* d_in, const int* in_sizes, int n_in,
                              void* d_out, int out_size)
{
    const float* q  = (const float*)d_in[0];
    const float* k  = (const float*)d_in[1];
    const float* v  = (const float*)d_in[2];
    // d_in[3] = mask (causal tril) — applied analytically
    const float* Wq = (const float*)d_in[4];
    const float* Wk = (const float*)d_in[5];
    const float* Wv = (const float*)d_in[6];
    const float* Wo = (const float*)d_in[7];
    float* out = (float*)d_out;

    float *qh, *kh, *vh, *ao;
    cudaGetSymbolAddress((void**)&qh, g_qh);
    cudaGetSymbolAddress((void**)&kh, g_kh);
    cudaGetSymbolAddress((void**)&vh, g_vh);
    cudaGetSymbolAddress((void**)&ao, g_ao);

    cudaFuncSetAttribute(gemm_proj3, cudaFuncAttributeMaxDynamicSharedMemorySize, GEMM_SMEM);
    cudaFuncSetAttribute(gemm_out, cudaFuncAttributeMaxDynamicSharedMemorySize, GEMM_SMEM);
    cudaFuncSetAttribute(attn_mma, cudaFuncAttributeMaxDynamicSharedMemorySize, ATTN_SMEM);

    round_x<<<dim3(NX / 8 / 256, 3), 256>>>(q, k, v);
    round_w<<<dim3(D_ * D_ / 8 / 256, 4), 256>>>(Wq, Wk, Wv, Wo);
    gemm_proj3<<<dim3(D_ / 128, (B_ * L_) / 128, 3), 256, GEMM_SMEM>>>(qh, kh, vh);
    attn_mma<<<NBLK, 256, ATTN_SMEM>>>(qh, kh, vh, ao);
    gemm_out<<<dim3(D_ / 128, (B_ * L_) / 128), 256, GEMM_SMEM>>>(ao, out);
}

// round 9
// speedup vs baseline: 1.9519x; 1.9519x over previous
#include <cuda_runtime.h>
#include <cuda_fp16.h>
#include <cstdint>
#include <cstddef>

#define B_ 4
#define L_ 2048
#define D_ 1024
#define H_ 16
#define HD_ 64
#define NX (B_*L_*D_)

// Scratch (allocation-free rule: __device__ globals)
__device__ __half g_qh[NX];        // [b,h,l,hd] fp16, pre-scaled 0.125
__device__ __half g_kh[NX];        // [b,h,l,hd] fp16
__device__ __half g_vh[NX];        // [b,h,hd,l] fp16 (TRANSPOSED)
__device__ __half g_ao[NX];        // [b,l,d] fp16
__device__ __half g_xh[3][NX];     // fp16 q,k,v
__device__ __half g_wh[4][D_*D_];  // fp16 Wq,Wk,Wv,Wo

// ---------------- helpers ----------------
__device__ __forceinline__ uint32_t s2u(const void* p) {
    uint32_t a;
    asm("{ .reg .u64 t; cvta.to.shared.u64 t, %1; cvt.u32.u64 %0, t; }" : "=r"(a) : "l"(p));
    return a;
}
__device__ __forceinline__ uint32_t pk2(float x, float y) {
    __half2 h = __floats2half2_rn(x, y);
    return *(uint32_t*)&h;
}
__device__ __forceinline__ void mma_f16(float* c, const uint32_t* a, const uint32_t* b) {
    asm volatile(
        "mma.sync.aligned.m16n8k16.row.col.f32.f16.f16.f32 "
        "{%0,%1,%2,%3}, {%4,%5,%6,%7}, {%8,%9}, {%0,%1,%2,%3};"
        : "+f"(c[0]), "+f"(c[1]), "+f"(c[2]), "+f"(c[3])
        : "r"(a[0]), "r"(a[1]), "r"(a[2]), "r"(a[3]), "r"(b[0]), "r"(b[1]));
}

// ---------------- fp16 convert passes ----------------
__global__ void __launch_bounds__(256) cvt_x(const float* __restrict__ q,
        const float* __restrict__ k, const float* __restrict__ v)
{
    const int z = blockIdx.y;
    const float* src = (z == 0) ? q : (z == 1) ? k : v;
    __half* dst = g_xh[z];
    int i = (blockIdx.x * 256 + threadIdx.x) * 8;
    float4 a = *(const float4*)(src + i);
    float4 b = *(const float4*)(src + i + 4);
    uint4 o;
    o.x = pk2(a.x, a.y); o.y = pk2(a.z, a.w);
    o.z = pk2(b.x, b.y); o.w = pk2(b.z, b.w);
    *(uint4*)(dst + i) = o;
}
__global__ void __launch_bounds__(256) cvt_w(const float* __restrict__ wq,
        const float* __restrict__ wk, const float* __restrict__ wv,
        const float* __restrict__ wo)
{
    const int z = blockIdx.y;
    const float* src = (z == 0) ? wq : (z == 1) ? wk : (z == 2) ? wv : wo;
    __half* dst = g_wh[z];
    int i = (blockIdx.x * 256 + threadIdx.x) * 8;
    float4 a = *(const float4*)(src + i);
    float4 b = *(const float4*)(src + i + 4);
    uint4 o;
    o.x = pk2(a.x, a.y); o.y = pk2(a.z, a.w);
    o.z = pk2(b.x, b.y); o.w = pk2(b.z, b.w);
    *(uint4*)(dst + i) = o;
}

// ---------------- fp16 mma.sync GEMM core: 128x128x(K=1024), chunk 64 ----------------
#define HP 72                       // smem pitch in halves
#define SSZ (128 * HP)              // one stage of one operand (halves)
#define GEMM_SMEM (4 * SSZ * 2)     // A0,A1,B0,B1 bytes = 73728
#define NIT2 (D_ / 64)              // 16 iterations

struct GemmAcc { float a[2][8][4]; };

__device__ __forceinline__ void gemm_core(const __half* __restrict__ Xa,
                                          const __half* __restrict__ Wb,
                                          __half* sm, int tid, GemmAcc& acc)
{
    const int wid = tid >> 5, lane = tid & 31;
    const int wm = wid >> 1, wn = wid & 1;
    const int g = lane >> 2, t4 = lane & 3;

    #pragma unroll
    for (int am = 0; am < 2; am++)
        #pragma unroll
        for (int na = 0; na < 8; na++)
            #pragma unroll
            for (int q = 0; q < 4; q++) acc.a[am][na][q] = 0.f;

    auto load_stage = [&](int ck, int s) {
        __half* As = sm + s * SSZ;
        __half* Bs = sm + 2 * SSZ + s * SSZ;
        #pragma unroll
        for (int i = 0; i < 4; i++) {
            int id = tid + i * 256;
            int r = id >> 3, u = id & 7;        // 8 x 16B chunks per 64-half row
            asm volatile("cp.async.cg.shared.global [%0], [%1], 16;"
                         :: "r"(s2u(As + r * HP + u * 8)),
                            "l"(Xa + (size_t)r * D_ + ck * 64 + u * 8));
            asm volatile("cp.async.cg.shared.global [%0], [%1], 16;"
                         :: "r"(s2u(Bs + r * HP + u * 8)),
                            "l"(Wb + (size_t)r * D_ + ck * 64 + u * 8));
        }
        asm volatile("cp.async.commit_group;");
    };

    load_stage(0, 0);

    for (int it = 0; it < NIT2; it++) {
        if (it + 1 < NIT2) {
            load_stage(it + 1, (it + 1) & 1);
            asm volatile("cp.async.wait_group 1;");
        } else {
            asm volatile("cp.async.wait_group 0;");
        }
        __syncthreads();

        const __half* As = sm + (it & 1) * SSZ;
        const __half* Bs = sm + 2 * SSZ + (it & 1) * SSZ;

        #pragma unroll
        for (int kk = 0; kk < 4; kk++) {        // 4 x k16
            const int co = kk * 16 + 2 * t4;
            uint32_t a[2][4];
            #pragma unroll
            for (int am = 0; am < 2; am++) {
                const __half* ap = As + (wm * 32 + am * 16 + g) * HP + co;
                a[am][0] = *(const uint32_t*)ap;
                a[am][1] = *(const uint32_t*)(ap + 8 * HP);
                a[am][2] = *(const uint32_t*)(ap + 8);
                a[am][3] = *(const uint32_t*)(ap + 8 * HP + 8);
            }
            uint32_t b[8][2];
            #pragma unroll
            for (int na = 0; na < 8; na++) {
                const __half* bp = Bs + (wn * 64 + na * 8 + g) * HP + co;
                b[na][0] = *(const uint32_t*)bp;
                b[na][1] = *(const uint32_t*)(bp + 8);
            }
            #pragma unroll
            for (int am = 0; am < 2; am++)
                #pragma unroll
                for (int na = 0; na < 8; na++)
                    mma_f16(acc.a[am][na], a[am], b[na]);
        }
        __syncthreads();
    }
}

// Merged Q/K/V projection: grid (8, 64, 3). Writes fp16 head layouts.
__global__ void __launch_bounds__(256, 2)
gemm_proj3()
{
    extern __shared__ __half smh[];
    const int tid = threadIdx.x;
    const int z = blockIdx.z;
    const int m0 = blockIdx.y * 128, n0 = blockIdx.x * 128;

    GemmAcc acc;
    gemm_core(g_xh[z] + (size_t)m0 * D_, g_wh[z] + (size_t)n0 * D_, smh, tid, acc);

    const int wid = tid >> 5, lane = tid & 31;
    const int wm = wid >> 1, wn = wid & 1;
    const int g = lane >> 2, t4 = lane & 3;
    const float scale = (z == 0) ? 0.125f : 1.0f;

    #pragma unroll
    for (int am = 0; am < 2; am++) {
        int r = m0 + wm * 32 + am * 16 + g;
        int b = r >> 11, l = r & 2047;
        #pragma unroll
        for (int na = 0; na < 8; na++) {
            int n = n0 + wn * 64 + na * 8 + 2 * t4;
            int h = n >> 6, hd = n & 63;
            if (z == 2) {
                // vh transposed: [b,h,hd,l]
                __half* pv = g_vh + (((size_t)b * H_ + h) * HD_ + hd) * L_ + l;
                pv[0]        = __float2half_rn(acc.a[am][na][0]);
                pv[L_]       = __float2half_rn(acc.a[am][na][1]);
                pv[8]        = __float2half_rn(acc.a[am][na][2]);
                pv[L_ + 8]   = __float2half_rn(acc.a[am][na][3]);
            } else {
                __half* Y = (z == 0) ? g_qh : g_kh;
                __half* p0 = Y + (((size_t)b * H_ + h) * L_ + l) * HD_ + hd;
                *(uint32_t*)p0 = pk2(acc.a[am][na][0] * scale, acc.a[am][na][1] * scale);
                __half* p1 = Y + (((size_t)b * H_ + h) * L_ + (l + 8)) * HD_ + hd;
                *(uint32_t*)p1 = pk2(acc.a[am][na][2] * scale, acc.a[am][na][3] * scale);
            }
        }
    }
}

// Output projection: fp16 in (g_ao, g_wh[3]), fp32 out.
__global__ void __launch_bounds__(256, 2)
gemm_out(float* __restrict__ Y)
{
    extern __shared__ __half smh[];
    const int tid = threadIdx.x;
    const int m0 = blockIdx.y * 128, n0 = blockIdx.x * 128;

    GemmAcc acc;
    gemm_core(g_ao + (size_t)m0 * D_, g_wh[3] + (size_t)n0 * D_, smh, tid, acc);

    const int wid = tid >> 5, lane = tid & 31;
    const int wm = wid >> 1, wn = wid & 1;
    const int g = lane >> 2, t4 = lane & 3;

    #pragma unroll
    for (int am = 0; am < 2; am++) {
        int r = m0 + wm * 32 + am * 16 + g;
        #pragma unroll
        for (int na = 0; na < 8; na++) {
            int n = n0 + wn * 64 + na * 8 + 2 * t4;
            float* p0 = Y + (size_t)r * D_ + n;
            p0[0] = acc.a[am][na][0]; p0[1] = acc.a[am][na][1];
            float* p1 = Y + (size_t)(r + 8) * D_ + n;
            p1[0] = acc.a[am][na][2]; p1[1] = acc.a[am][na][3];
        }
    }
}

// ---------------- fp16 mma.sync flash attention (persistent, snake) ----------------
// 128 threads, 4 warps x 32 rows, KV tile 64, double-buffered.
#define KSTG (2 * 64 * HP)                       // K + Vt, one stage (halves)
#define ATTN_SMEM ((128 * HP + 2 * KSTG) * 2)    // bytes = 55296
#define NBLK 296

__global__ void __launch_bounds__(128, 2) attn_mma(__half* __restrict__ ao)
{
    extern __shared__ __half smh[];
    __half* Qs = smh;
    __half* KV = smh + 128 * HP;

    const int tid = threadIdx.x;
    const int wid = tid >> 5, lane = tid & 31;
    const int g = lane >> 2, t4 = lane & 3;
    const int p = blockIdx.x;

    #pragma unroll 1
    for (int round = 0; round < 4; round++) {
        int rank = (round == 0) ? p
                 : (round == 1) ? (591 - p)
                 : (round == 2) ? (592 + p)
                 : (1183 - p);
        if (rank >= 1024) continue;
        const int qt = 15 - (rank >> 6);
        const int bh = rank & 63;
        const int q0 = qt * 128;

        const __half* Qb = g_qh + ((size_t)bh * L_ + q0) * HD_;
        const __half* Kb = g_kh + (size_t)bh * L_ * HD_;
        const __half* Vb = g_vh + (size_t)bh * HD_ * L_;   // [hd][l]

        __syncthreads();   // smem free from previous tile

        #pragma unroll
        for (int i = 0; i < 8; i++) {
            int e = tid + i * 128;
            int r = e >> 3, u = e & 7;
            *(uint4*)(Qs + r * HP + u * 8) = *(const uint4*)(Qb + (size_t)r * 64 + u * 8);
        }

        auto ldkv = [&](int kt, int st) {
            __half* Ks = KV + st * KSTG;
            __half* Vs = Ks + 64 * HP;
            const __half* kg = Kb + (size_t)kt * 64 * 64;
            const __half* vg = Vb + kt * 64;           // row hd, cols kt*64..
            #pragma unroll
            for (int i = 0; i < 4; i++) {
                int e = tid + i * 128;
                int r = e >> 3, u = e & 7;
                asm volatile("cp.async.cg.shared.global [%0], [%1], 16;"
                             :: "r"(s2u(Ks + r * HP + u * 8)),
                                "l"(kg + (size_t)r * 64 + u * 8));
                asm volatile("cp.async.cg.shared.global [%0], [%1], 16;"
                             :: "r"(s2u(Vs + r * HP + u * 8)),
                                "l"(vg + (size_t)r * L_ + u * 8));
            }
            asm volatile("cp.async.commit_group;");
        };

        float mrun[4], lrun[4], O[2][8][4];
        #pragma unroll
        for (int i = 0; i < 4; i++) { mrun[i] = -1e30f; lrun[i] = 0.f; }
        #pragma unroll
        for (int mt = 0; mt < 2; mt++)
            #pragma unroll
            for (int nt = 0; nt < 8; nt++)
                #pragma unroll
                for (int e = 0; e < 4; e++) O[mt][nt][e] = 0.f;

        const int ntiles = 2 * qt + 2;
        ldkv(0, 0);

        for (int kt = 0; kt < ntiles; kt++) {
            asm volatile("cp.async.wait_group 0;");
            __syncthreads();
            if (kt + 1 < ntiles) ldkv(kt + 1, (kt + 1) & 1);
            const __half* Ks = KV + (kt & 1) * KSTG;
            const __half* Vs = Ks + 64 * HP;

            // ---- S = Q K^T ----
            float S[2][8][4];
            #pragma unroll
            for (int mt = 0; mt < 2; mt++)
                #pragma unroll
                for (int nt = 0; nt < 8; nt++)
                    #pragma unroll
                    for (int e = 0; e < 4; e++) S[mt][nt][e] = 0.f;

            #pragma unroll
            for (int kc = 0; kc < 4; kc++) {       // 4 x k16 over hd=64
                const int co = kc * 16 + 2 * t4;
                uint32_t af[2][4];
                #pragma unroll
                for (int mt = 0; mt < 2; mt++) {
                    const __half* ap = Qs + (wid * 32 + mt * 16 + g) * HP + co;
                    af[mt][0] = *(const uint32_t*)ap;
                    af[mt][1] = *(const uint32_t*)(ap + 8 * HP);
                    af[mt][2] = *(const uint32_t*)(ap + 8);
                    af[mt][3] = *(const uint32_t*)(ap + 8 * HP + 8);
                }
                #pragma unroll
                for (int nt = 0; nt < 8; nt++) {
                    const __half* bp = Ks + (nt * 8 + g) * HP + co;
                    uint32_t bf[2];
                    bf[0] = *(const uint32_t*)bp;
                    bf[1] = *(const uint32_t*)(bp + 8);
                    mma_f16(S[0][nt], af[0], bf);
                    mma_f16(S[1][nt], af[1], bf);
                }
            }

            // ---- online softmax ----
            const bool maskt = (kt >= ntiles - 2);
            #pragma unroll
            for (int mt = 0; mt < 2; mt++)
                #pragma unroll
                for (int rr = 0; rr < 2; rr++) {
                    const int si = mt * 2 + rr;
                    const int rowg = q0 + wid * 32 + mt * 16 + rr * 8 + g;
                    float mloc = -1e30f;
                    #pragma unroll
                    for (int nt = 0; nt < 8; nt++)
                        #pragma unroll
                        for (int e = 0; e < 2; e++) {
                            float vv = S[mt][nt][rr * 2 + e];
                            if (maskt && (kt * 64 + nt * 8 + 2 * t4 + e) > rowg) vv = -1e30f;
                            S[mt][nt][rr * 2 + e] = vv;
                            mloc = fmaxf(mloc, vv);
                        }
                    mloc = fmaxf(mloc, __shfl_xor_sync(0xffffffffu, mloc, 1));
                    mloc = fmaxf(mloc, __shfl_xor_sync(0xffffffffu, mloc, 2));
                    float mnew = fmaxf(mrun[si], mloc);
                    float corr = __expf(mrun[si] - mnew);
                    float sum = 0.f;
                    #pragma unroll
                    for (int nt = 0; nt < 8; nt++)
                        #pragma unroll
                        for (int e = 0; e < 2; e++) {
                            float pe = __expf(S[mt][nt][rr * 2 + e] - mnew);
                            S[mt][nt][rr * 2 + e] = pe;
                            sum += pe;
                        }
                    sum += __shfl_xor_sync(0xffffffffu, sum, 1);
                    sum += __shfl_xor_sync(0xffffffffu, sum, 2);
                    lrun[si] = lrun[si] * corr + sum;
                    mrun[si] = mnew;
                    #pragma unroll
                    for (int nt = 0; nt < 8; nt++)
                        #pragma unroll
                        for (int e = 0; e < 2; e++)
                            O[mt][nt][rr * 2 + e] *= corr;
                }

            // ---- O += P V : pack C-frags to f16 A-frags (NO shuffles) ----
            #pragma unroll
            for (int kc = 0; kc < 4; kc++) {       // k16 over s=64: nt pair (2kc, 2kc+1)
                uint32_t a[2][4];
                #pragma unroll
                for (int mt = 0; mt < 2; mt++) {
                    a[mt][0] = pk2(S[mt][2 * kc][0],     S[mt][2 * kc][1]);
                    a[mt][1] = pk2(S[mt][2 * kc][2],     S[mt][2 * kc][3]);
                    a[mt][2] = pk2(S[mt][2 * kc + 1][0], S[mt][2 * kc + 1][1]);
                    a[mt][3] = pk2(S[mt][2 * kc + 1][2], S[mt][2 * kc + 1][3]);
                }
                const int co = kc * 16 + 2 * t4;
                #pragma unroll
                for (int nt = 0; nt < 8; nt++) {
                    const __half* bp = Vs + (nt * 8 + g) * HP + co;   // Vt[d][s]
                    uint32_t bf[2];
                    bf[0] = *(const uint32_t*)bp;
                    bf[1] = *(const uint32_t*)(bp + 8);
                    mma_f16(O[0][nt], a[0], bf);
                    mma_f16(O[1][nt], a[1], bf);
                }
            }
        }

        // ---- epilogue: normalize + fp16 write [b, l, d] ----
        const int b = bh >> 4, h = bh & 15;
        #pragma unroll
        for (int mt = 0; mt < 2; mt++)
            #pragma unroll
            for (int rr = 0; rr < 2; rr++) {
                const int si = mt * 2 + rr;
                float inv = 1.f / lrun[si];
                int row = q0 + wid * 32 + mt * 16 + rr * 8 + g;
                __half* op = ao + ((size_t)b * L_ + row) * D_ + h * 64 + 2 * t4;
                #pragma unroll
                for (int nt = 0; nt < 8; nt++)
                    *(uint32_t*)(op + nt * 8) =
                        pk2(O[mt][nt][rr * 2] * inv, O[mt][nt][rr * 2 + 1] * inv);
            }
    }
}

// ---------------- launch ----------------
extern "C" void kernel_launch(void* const* d_in, const int* in_sizes, int n_in,
                              void* d_out, int out_size)
{
    const float* q  = (const float*)d_in[0];
    const float* k  = (const float*)d_in[1];
    const float* v  = (const float*)d_in[2];
    // d_in[3] = mask (causal tril) — applied analytically
    const float* Wq = (const float*)d_in[4];
    const float* Wk = (const float*)d_in[5];
    const float* Wv = (const float*)d_in[6];
    const float* Wo = (const float*)d_in[7];
    float* out = (float*)d_out;

    __half* ao;
    cudaGetSymbolAddress((void**)&ao, g_ao);

    cudaFuncSetAttribute(gemm_proj3, cudaFuncAttributeMaxDynamicSharedMemorySize, GEMM_SMEM);
    cudaFuncSetAttribute(gemm_out, cudaFuncAttributeMaxDynamicSharedMemorySize, GEMM_SMEM);
    cudaFuncSetAttribute(attn_mma, cudaFuncAttributeMaxDynamicSharedMemorySize, ATTN_SMEM);

    cvt_x<<<dim3(NX / 8 / 256, 3), 256>>>(q, k, v);
    cvt_w<<<dim3(D_ * D_ / 8 / 256, 4), 256>>>(Wq, Wk, Wv, Wo);
    gemm_proj3<<<dim3(D_ / 128, (B_ * L_) / 128, 3), 256, GEMM_SMEM>>>();
    attn_mma<<<NBLK, 128, ATTN_SMEM>>>(ao);
    gemm_out<<<dim3(D_ / 128, (B_ * L_) / 128), 256, GEMM_SMEM>>>(out);
}

// round 10
// speedup vs baseline: 2.0968x; 1.0742x over previous
#include <cuda_runtime.h>
#include <cuda_fp16.h>
#include <cstdint>
#include <cstddef>

#define B_ 4
#define L_ 2048
#define D_ 1024
#define H_ 16
#define HD_ 64
#define NX (B_*L_*D_)

// Scratch (allocation-free rule: __device__ globals)
__device__ __half g_qh[NX];        // [b,h,l,hd] fp16, pre-scaled 0.125*log2(e)
__device__ __half g_kh[NX];        // [b,h,l,hd] fp16
__device__ __half g_vh[NX];        // [b,h,hd,l] fp16 (TRANSPOSED)
__device__ __half g_ao[NX];        // [b,l,d] fp16
__device__ __half g_xh[3][NX];     // fp16 q,k,v
__device__ __half g_wh[4][D_*D_];  // fp16 Wq,Wk,Wv,Wo

#define QSCALE 0.18033688011112042f   // 0.125 * log2(e)

// ---------------- helpers ----------------
__device__ __forceinline__ uint32_t s2u(const void* p) {
    uint32_t a;
    asm("{ .reg .u64 t; cvta.to.shared.u64 t, %1; cvt.u32.u64 %0, t; }" : "=r"(a) : "l"(p));
    return a;
}
__device__ __forceinline__ uint32_t pk2(float x, float y) {
    __half2 h = __floats2half2_rn(x, y);
    return *(uint32_t*)&h;
}
__device__ __forceinline__ float ex2f(float x) {
    float r; asm("ex2.approx.f32 %0, %1;" : "=f"(r) : "f"(x)); return r;
}
__device__ __forceinline__ void mma_f16(float* c, const uint32_t* a, const uint32_t* b) {
    asm volatile(
        "mma.sync.aligned.m16n8k16.row.col.f32.f16.f16.f32 "
        "{%0,%1,%2,%3}, {%4,%5,%6,%7}, {%8,%9}, {%0,%1,%2,%3};"
        : "+f"(c[0]), "+f"(c[1]), "+f"(c[2]), "+f"(c[3])
        : "r"(a[0]), "r"(a[1]), "r"(a[2]), "r"(a[3]), "r"(b[0]), "r"(b[1]));
}
__device__ __forceinline__ void ldm4(uint32_t& r0, uint32_t& r1, uint32_t& r2,
                                     uint32_t& r3, uint32_t addr) {
    asm volatile("ldmatrix.sync.aligned.m8n8.x4.shared.b16 {%0,%1,%2,%3}, [%4];"
                 : "=r"(r0), "=r"(r1), "=r"(r2), "=r"(r3) : "r"(addr));
}

// ---------------- fp16 convert passes ----------------
__global__ void __launch_bounds__(256) cvt_x(const float* __restrict__ q,
        const float* __restrict__ k, const float* __restrict__ v)
{
    const int z = blockIdx.y;
    const float* src = (z == 0) ? q : (z == 1) ? k : v;
    __half* dst = g_xh[z];
    int i = (blockIdx.x * 256 + threadIdx.x) * 8;
    float4 a = *(const float4*)(src + i);
    float4 b = *(const float4*)(src + i + 4);
    uint4 o;
    o.x = pk2(a.x, a.y); o.y = pk2(a.z, a.w);
    o.z = pk2(b.x, b.y); o.w = pk2(b.z, b.w);
    *(uint4*)(dst + i) = o;
}
__global__ void __launch_bounds__(256) cvt_w(const float* __restrict__ wq,
        const float* __restrict__ wk, const float* __restrict__ wv,
        const float* __restrict__ wo)
{
    const int z = blockIdx.y;
    const float* src = (z == 0) ? wq : (z == 1) ? wk : (z == 2) ? wv : wo;
    __half* dst = g_wh[z];
    int i = (blockIdx.x * 256 + threadIdx.x) * 8;
    float4 a = *(const float4*)(src + i);
    float4 b = *(const float4*)(src + i + 4);
    uint4 o;
    o.x = pk2(a.x, a.y); o.y = pk2(a.z, a.w);
    o.z = pk2(b.x, b.y); o.w = pk2(b.z, b.w);
    *(uint4*)(dst + i) = o;
}

// ---------------- fp16 mma.sync GEMM core (ldmatrix), 128x128, chunk 64 ----------------
#define HP 72
#define SSZ (128 * HP)
#define GEMM_SMEM (4 * SSZ * 2)
#define NIT2 (D_ / 64)

struct GemmAcc { float a[2][8][4]; };

__device__ __forceinline__ void gemm_core(const __half* __restrict__ Xa,
                                          const __half* __restrict__ Wb,
                                          __half* sm, int tid, GemmAcc& acc)
{
    const int wid = tid >> 5, lane = tid & 31;
    const int wm = wid >> 1, wn = wid & 1;
    const int lr = lane & 7, lt = lane >> 3;
    const uint32_t offA = (((lt & 1) * 8 + lr) * HP + (lt >> 1) * 8) * 2;
    const uint32_t offB = (((lt >> 1) * 8 + lr) * HP + (lt & 1) * 8) * 2;

    #pragma unroll
    for (int am = 0; am < 2; am++)
        #pragma unroll
        for (int na = 0; na < 8; na++)
            #pragma unroll
            for (int q = 0; q < 4; q++) acc.a[am][na][q] = 0.f;

    auto load_stage = [&](int ck, int s) {
        __half* As = sm + s * SSZ;
        __half* Bs = sm + 2 * SSZ + s * SSZ;
        #pragma unroll
        for (int i = 0; i < 4; i++) {
            int id = tid + i * 256;
            int r = id >> 3, u = id & 7;
            asm volatile("cp.async.cg.shared.global [%0], [%1], 16;"
                         :: "r"(s2u(As + r * HP + u * 8)),
                            "l"(Xa + (size_t)r * D_ + ck * 64 + u * 8));
            asm volatile("cp.async.cg.shared.global [%0], [%1], 16;"
                         :: "r"(s2u(Bs + r * HP + u * 8)),
                            "l"(Wb + (size_t)r * D_ + ck * 64 + u * 8));
        }
        asm volatile("cp.async.commit_group;");
    };

    load_stage(0, 0);

    for (int it = 0; it < NIT2; it++) {
        if (it + 1 < NIT2) {
            load_stage(it + 1, (it + 1) & 1);
            asm volatile("cp.async.wait_group 1;");
        } else {
            asm volatile("cp.async.wait_group 0;");
        }
        __syncthreads();

        const __half* As = sm + (it & 1) * SSZ;
        const __half* Bs = sm + 2 * SSZ + (it & 1) * SSZ;
        const uint32_t abase = s2u(As) + (uint32_t)(wm * 32 * HP) * 2 + offA;
        const uint32_t bbase = s2u(Bs) + (uint32_t)(wn * 64 * HP) * 2 + offB;

        #pragma unroll
        for (int kk = 0; kk < 4; kk++) {
            uint32_t a[2][4];
            ldm4(a[0][0], a[0][1], a[0][2], a[0][3], abase + kk * 32);
            ldm4(a[1][0], a[1][1], a[1][2], a[1][3], abase + 16 * HP * 2 + kk * 32);
            uint32_t b[8][2];
            #pragma unroll
            for (int j = 0; j < 4; j++) {
                uint32_t r0, r1, r2, r3;
                ldm4(r0, r1, r2, r3, bbase + j * 16 * HP * 2 + kk * 32);
                b[2 * j][0] = r0; b[2 * j][1] = r1;
                b[2 * j + 1][0] = r2; b[2 * j + 1][1] = r3;
            }
            #pragma unroll
            for (int am = 0; am < 2; am++)
                #pragma unroll
                for (int na = 0; na < 8; na++)
                    mma_f16(acc.a[am][na], a[am], b[na]);
        }
        __syncthreads();
    }
}

// Merged Q/K/V projection: grid (8, 64, 3). Writes fp16 head layouts.
__global__ void __launch_bounds__(256, 2)
gemm_proj3()
{
    extern __shared__ __half smh[];
    const int tid = threadIdx.x;
    const int z = blockIdx.z;
    const int m0 = blockIdx.y * 128, n0 = blockIdx.x * 128;

    GemmAcc acc;
    gemm_core(g_xh[z] + (size_t)m0 * D_, g_wh[z] + (size_t)n0 * D_, smh, tid, acc);

    const int wid = tid >> 5, lane = tid & 31;
    const int wm = wid >> 1, wn = wid & 1;
    const int g = lane >> 2, t4 = lane & 3;
    const float scale = (z == 0) ? QSCALE : 1.0f;

    #pragma unroll
    for (int am = 0; am < 2; am++) {
        int r = m0 + wm * 32 + am * 16 + g;
        int b = r >> 11, l = r & 2047;
        #pragma unroll
        for (int na = 0; na < 8; na++) {
            int n = n0 + wn * 64 + na * 8 + 2 * t4;
            int h = n >> 6, hd = n & 63;
            if (z == 2) {
                __half* pv = g_vh + (((size_t)b * H_ + h) * HD_ + hd) * L_ + l;
                pv[0]      = __float2half_rn(acc.a[am][na][0]);
                pv[L_]     = __float2half_rn(acc.a[am][na][1]);
                pv[8]      = __float2half_rn(acc.a[am][na][2]);
                pv[L_ + 8] = __float2half_rn(acc.a[am][na][3]);
            } else {
                __half* Y = (z == 0) ? g_qh : g_kh;
                __half* p0 = Y + (((size_t)b * H_ + h) * L_ + l) * HD_ + hd;
                *(uint32_t*)p0 = pk2(acc.a[am][na][0] * scale, acc.a[am][na][1] * scale);
                __half* p1 = Y + (((size_t)b * H_ + h) * L_ + (l + 8)) * HD_ + hd;
                *(uint32_t*)p1 = pk2(acc.a[am][na][2] * scale, acc.a[am][na][3] * scale);
            }
        }
    }
}

// Output projection: fp16 in (g_ao, g_wh[3]), fp32 out.
__global__ void __launch_bounds__(256, 2)
gemm_out(float* __restrict__ Y)
{
    extern __shared__ __half smh[];
    const int tid = threadIdx.x;
    const int m0 = blockIdx.y * 128, n0 = blockIdx.x * 128;

    GemmAcc acc;
    gemm_core(g_ao + (size_t)m0 * D_, g_wh[3] + (size_t)n0 * D_, smh, tid, acc);

    const int wid = tid >> 5, lane = tid & 31;
    const int wm = wid >> 1, wn = wid & 1;
    const int g = lane >> 2, t4 = lane & 3;

    #pragma unroll
    for (int am = 0; am < 2; am++) {
        int r = m0 + wm * 32 + am * 16 + g;
        #pragma unroll
        for (int na = 0; na < 8; na++) {
            int n = n0 + wn * 64 + na * 8 + 2 * t4;
            float* p0 = Y + (size_t)r * D_ + n;
            p0[0] = acc.a[am][na][0]; p0[1] = acc.a[am][na][1];
            float* p1 = Y + (size_t)(r + 8) * D_ + n;
            p1[0] = acc.a[am][na][2]; p1[1] = acc.a[am][na][3];
        }
    }
}

// ---------------- fp16 flash attention (ldmatrix + log2 softmax) ----------------
#define KSTG (2 * 64 * HP)
#define ATTN_SMEM ((128 * HP + 2 * KSTG) * 2)
#define NBLK 296

__global__ void __launch_bounds__(128, 2) attn_mma(__half* __restrict__ ao)
{
    extern __shared__ __half smh[];
    __half* Qs = smh;
    __half* KV = smh + 128 * HP;

    const int tid = threadIdx.x;
    const int wid = tid >> 5, lane = tid & 31;
    const int g = lane >> 2, t4 = lane & 3;
    const int lr = lane & 7, lt = lane >> 3;
    const uint32_t offA = (((lt & 1) * 8 + lr) * HP + (lt >> 1) * 8) * 2;
    const uint32_t offB = (((lt >> 1) * 8 + lr) * HP + (lt & 1) * 8) * 2;
    const int p = blockIdx.x;

    const uint32_t qbase0 = s2u(Qs) + (uint32_t)(wid * 32 * HP) * 2 + offA;

    #pragma unroll 1
    for (int round = 0; round < 4; round++) {
        int rank = (round == 0) ? p
                 : (round == 1) ? (591 - p)
                 : (round == 2) ? (592 + p)
                 : (1183 - p);
        if (rank >= 1024) continue;
        const int qt = 15 - (rank >> 6);
        const int bh = rank & 63;
        const int q0 = qt * 128;

        const __half* Qb = g_qh + ((size_t)bh * L_ + q0) * HD_;
        const __half* Kb = g_kh + (size_t)bh * L_ * HD_;
        const __half* Vb = g_vh + (size_t)bh * HD_ * L_;

        __syncthreads();

        #pragma unroll
        for (int i = 0; i < 8; i++) {
            int e = tid + i * 128;
            int r = e >> 3, u = e & 7;
            *(uint4*)(Qs + r * HP + u * 8) = *(const uint4*)(Qb + (size_t)r * 64 + u * 8);
        }

        auto ldkv = [&](int kt, int st) {
            __half* Ks = KV + st * KSTG;
            __half* Vs = Ks + 64 * HP;
            const __half* kg = Kb + (size_t)kt * 64 * 64;
            const __half* vg = Vb + kt * 64;
            #pragma unroll
            for (int i = 0; i < 4; i++) {
                int e = tid + i * 128;
                int r = e >> 3, u = e & 7;
                asm volatile("cp.async.cg.shared.global [%0], [%1], 16;"
                             :: "r"(s2u(Ks + r * HP + u * 8)),
                                "l"(kg + (size_t)r * 64 + u * 8));
                asm volatile("cp.async.cg.shared.global [%0], [%1], 16;"
                             :: "r"(s2u(Vs + r * HP + u * 8)),
                                "l"(vg + (size_t)r * L_ + u * 8));
            }
            asm volatile("cp.async.commit_group;");
        };

        float mrun[4], lrun[4], O[2][8][4];
        #pragma unroll
        for (int i = 0; i < 4; i++) { mrun[i] = -1e30f; lrun[i] = 0.f; }
        #pragma unroll
        for (int mt = 0; mt < 2; mt++)
            #pragma unroll
            for (int nt = 0; nt < 8; nt++)
                #pragma unroll
                for (int e = 0; e < 4; e++) O[mt][nt][e] = 0.f;

        const int ntiles = 2 * qt + 2;
        ldkv(0, 0);

        for (int kt = 0; kt < ntiles; kt++) {
            asm volatile("cp.async.wait_group 0;");
            __syncthreads();
            if (kt + 1 < ntiles) ldkv(kt + 1, (kt + 1) & 1);
            const __half* Ks = KV + (kt & 1) * KSTG;
            const __half* Vs = Ks + 64 * HP;
            const uint32_t kbase = s2u(Ks) + offB;
            const uint32_t vbase = s2u(Vs) + offB;

            // ---- S = Q K^T ----
            float S[2][8][4];
            #pragma unroll
            for (int mt = 0; mt < 2; mt++)
                #pragma unroll
                for (int nt = 0; nt < 8; nt++)
                    #pragma unroll
                    for (int e = 0; e < 4; e++) S[mt][nt][e] = 0.f;

            #pragma unroll
            for (int kc = 0; kc < 4; kc++) {
                uint32_t af[2][4];
                ldm4(af[0][0], af[0][1], af[0][2], af[0][3], qbase0 + kc * 32);
                ldm4(af[1][0], af[1][1], af[1][2], af[1][3],
                     qbase0 + 16 * HP * 2 + kc * 32);
                #pragma unroll
                for (int j = 0; j < 4; j++) {
                    uint32_t r0, r1, r2, r3;
                    ldm4(r0, r1, r2, r3, kbase + j * 16 * HP * 2 + kc * 32);
                    uint32_t bf0[2] = {r0, r1}, bf1[2] = {r2, r3};
                    mma_f16(S[0][2 * j], af[0], bf0);
                    mma_f16(S[0][2 * j + 1], af[0], bf1);
                    mma_f16(S[1][2 * j], af[1], bf0);
                    mma_f16(S[1][2 * j + 1], af[1], bf1);
                }
            }

            // ---- online softmax (log2 domain; mask-specialized) ----
            const bool maskt = (kt >= ntiles - 2);
            uint32_t Ppk[2][8][2];
            #pragma unroll
            for (int mt = 0; mt < 2; mt++)
                #pragma unroll
                for (int rr = 0; rr < 2; rr++) {
                    const int si = mt * 2 + rr;
                    float mloc = -1e30f;
                    if (maskt) {
                        const int rowg = q0 + wid * 32 + mt * 16 + rr * 8 + g;
                        #pragma unroll
                        for (int nt = 0; nt < 8; nt++)
                            #pragma unroll
                            for (int e = 0; e < 2; e++) {
                                float vv = S[mt][nt][rr * 2 + e];
                                if ((kt * 64 + nt * 8 + 2 * t4 + e) > rowg) vv = -1e30f;
                                S[mt][nt][rr * 2 + e] = vv;
                                mloc = fmaxf(mloc, vv);
                            }
                    } else {
                        #pragma unroll
                        for (int nt = 0; nt < 8; nt++)
                            #pragma unroll
                            for (int e = 0; e < 2; e++)
                                mloc = fmaxf(mloc, S[mt][nt][rr * 2 + e]);
                    }
                    mloc = fmaxf(mloc, __shfl_xor_sync(0xffffffffu, mloc, 1));
                    mloc = fmaxf(mloc, __shfl_xor_sync(0xffffffffu, mloc, 2));
                    float mnew = fmaxf(mrun[si], mloc);
                    float corrf = ex2f(mrun[si] - mnew);
                    float sum = 0.f;
                    #pragma unroll
                    for (int nt = 0; nt < 8; nt++) {
                        float p0 = ex2f(S[mt][nt][rr * 2] - mnew);
                        float p1 = ex2f(S[mt][nt][rr * 2 + 1] - mnew);
                        sum += p0; sum += p1;
                        Ppk[mt][nt][rr] = pk2(p0, p1);
                    }
                    sum += __shfl_xor_sync(0xffffffffu, sum, 1);
                    sum += __shfl_xor_sync(0xffffffffu, sum, 2);
                    lrun[si] = lrun[si] * corrf + sum;
                    mrun[si] = mnew;
                    #pragma unroll
                    for (int nt = 0; nt < 8; nt++)
                        #pragma unroll
                        for (int e = 0; e < 2; e++)
                            O[mt][nt][rr * 2 + e] *= corrf;
                }

            // ---- O += P V (packed P is the A-frag; V via ldmatrix) ----
            #pragma unroll
            for (int kc = 0; kc < 4; kc++) {
                uint32_t a[2][4];
                #pragma unroll
                for (int mt = 0; mt < 2; mt++) {
                    a[mt][0] = Ppk[mt][2 * kc][0];
                    a[mt][1] = Ppk[mt][2 * kc][1];
                    a[mt][2] = Ppk[mt][2 * kc + 1][0];
                    a[mt][3] = Ppk[mt][2 * kc + 1][1];
                }
                #pragma unroll
                for (int j = 0; j < 4; j++) {
                    uint32_t r0, r1, r2, r3;
                    ldm4(r0, r1, r2, r3, vbase + j * 16 * HP * 2 + kc * 32);
                    uint32_t bf0[2] = {r0, r1}, bf1[2] = {r2, r3};
                    mma_f16(O[0][2 * j], a[0], bf0);
                    mma_f16(O[0][2 * j + 1], a[0], bf1);
                    mma_f16(O[1][2 * j], a[1], bf0);
                    mma_f16(O[1][2 * j + 1], a[1], bf1);
                }
            }
        }

        // ---- epilogue: normalize + fp16 write [b, l, d] ----
        const int b = bh >> 4, h = bh & 15;
        #pragma unroll
        for (int mt = 0; mt < 2; mt++)
            #pragma unroll
            for (int rr = 0; rr < 2; rr++) {
                const int si = mt * 2 + rr;
                float inv = 1.f / lrun[si];
                int row = q0 + wid * 32 + mt * 16 + rr * 8 + g;
                __half* op = ao + ((size_t)b * L_ + row) * D_ + h * 64 + 2 * t4;
                #pragma unroll
                for (int nt = 0; nt < 8; nt++)
                    *(uint32_t*)(op + nt * 8) =
                        pk2(O[mt][nt][rr * 2] * inv, O[mt][nt][rr * 2 + 1] * inv);
            }
    }
}

// ---------------- launch ----------------
extern "C" void kernel_launch(void* const* d_in, const int* in_sizes, int n_in,
                              void* d_out, int out_size)
{
    const float* q  = (const float*)d_in[0];
    const float* k  = (const float*)d_in[1];
    const float* v  = (const float*)d_in[2];
    // d_in[3] = mask (causal tril) — applied analytically
    const float* Wq = (const float*)d_in[4];
    const float* Wk = (const float*)d_in[5];
    const float* Wv = (const float*)d_in[6];
    const float* Wo = (const float*)d_in[7];
    float* out = (float*)d_out;

    __half* ao;
    cudaGetSymbolAddress((void**)&ao, g_ao);

    cudaFuncSetAttribute(gemm_proj3, cudaFuncAttributeMaxDynamicSharedMemorySize, GEMM_SMEM);
    cudaFuncSetAttribute(gemm_out, cudaFuncAttributeMaxDynamicSharedMemorySize, GEMM_SMEM);
    cudaFuncSetAttribute(attn_mma, cudaFuncAttributeMaxDynamicSharedMemorySize, ATTN_SMEM);

    cvt_x<<<dim3(NX / 8 / 256, 3), 256>>>(q, k, v);
    cvt_w<<<dim3(D_ * D_ / 8 / 256, 4), 256>>>(Wq, Wk, Wv, Wo);
    gemm_proj3<<<dim3(D_ / 128, (B_ * L_) / 128, 3), 256, GEMM_SMEM>>>();
    attn_mma<<<NBLK, 128, ATTN_SMEM>>>(ao);
    gemm_out<<<dim3(D_ / 128, (B_ * L_) / 128), 256, GEMM_SMEM>>>(out);
}

// round 12
// speedup vs baseline: 2.1008x; 1.0019x over previous
#include <cuda_runtime.h>
#include <cuda_fp16.h>
#include <cstdint>
#include <cstddef>

#define B_ 4
#define L_ 2048
#define D_ 1024
#define H_ 16
#define HD_ 64
#define NX (B_*L_*D_)

// Scratch (allocation-free rule: __device__ globals)
__device__ __half g_qh[NX];        // [b,h,l,hd] fp16, pre-scaled 0.125*log2(e)
__device__ __half g_kh[NX];        // [b,h,l,hd] fp16
__device__ __half g_vh[NX];        // [b,h,hd,l] fp16 (TRANSPOSED)
__device__ __half g_ao[NX];        // [b,l,d] fp16
__device__ __half g_xh[3][NX];     // fp16 q,k,v
__device__ __half g_wh[4][D_*D_];  // fp16 Wq,Wk,Wv,Wo

#define QSCALE 0.18033688011112042f   // 0.125 * log2(e)

// ---------------- helpers ----------------
__device__ __forceinline__ uint32_t s2u(const void* p) {
    uint32_t a;
    asm("{ .reg .u64 t; cvta.to.shared.u64 t, %1; cvt.u32.u64 %0, t; }" : "=r"(a) : "l"(p));
    return a;
}
__device__ __forceinline__ uint32_t pk2(float x, float y) {
    __half2 h = __floats2half2_rn(x, y);
    return *(uint32_t*)&h;
}
__device__ __forceinline__ float ex2f(float x) {
    float r; asm("ex2.approx.f32 %0, %1;" : "=f"(r) : "f"(x)); return r;
}
__device__ __forceinline__ void mma_f16(float* c, const uint32_t* a, const uint32_t* b) {
    asm volatile(
        "mma.sync.aligned.m16n8k16.row.col.f32.f16.f16.f32 "
        "{%0,%1,%2,%3}, {%4,%5,%6,%7}, {%8,%9}, {%0,%1,%2,%3};"
        : "+f"(c[0]), "+f"(c[1]), "+f"(c[2]), "+f"(c[3])
        : "r"(a[0]), "r"(a[1]), "r"(a[2]), "r"(a[3]), "r"(b[0]), "r"(b[1]));
}
__device__ __forceinline__ void ldm4(uint32_t& r0, uint32_t& r1, uint32_t& r2,
                                     uint32_t& r3, uint32_t addr) {
    asm volatile("ldmatrix.sync.aligned.m8n8.x4.shared.b16 {%0,%1,%2,%3}, [%4];"
                 : "=r"(r0), "=r"(r1), "=r"(r2), "=r"(r3) : "r"(addr));
}

// ---------------- fp16 convert passes ----------------
__global__ void __launch_bounds__(256) cvt_x(const float* __restrict__ q,
        const float* __restrict__ k, const float* __restrict__ v)
{
    const int z = blockIdx.y;
    const float* src = (z == 0) ? q : (z == 1) ? k : v;
    __half* dst = g_xh[z];
    int i = (blockIdx.x * 256 + threadIdx.x) * 8;
    float4 a = *(const float4*)(src + i);
    float4 b = *(const float4*)(src + i + 4);
    uint4 o;
    o.x = pk2(a.x, a.y); o.y = pk2(a.z, a.w);
    o.z = pk2(b.x, b.y); o.w = pk2(b.z, b.w);
    *(uint4*)(dst + i) = o;
}
__global__ void __launch_bounds__(256) cvt_w(const float* __restrict__ wq,
        const float* __restrict__ wk, const float* __restrict__ wv,
        const float* __restrict__ wo)
{
    const int z = blockIdx.y;
    const float* src = (z == 0) ? wq : (z == 1) ? wk : (z == 2) ? wv : wo;
    __half* dst = g_wh[z];
    int i = (blockIdx.x * 256 + threadIdx.x) * 8;
    float4 a = *(const float4*)(src + i);
    float4 b = *(const float4*)(src + i + 4);
    uint4 o;
    o.x = pk2(a.x, a.y); o.y = pk2(a.z, a.w);
    o.z = pk2(b.x, b.y); o.w = pk2(b.z, b.w);
    *(uint4*)(dst + i) = o;
}

// ---------------- fp16 mma.sync GEMM core (ldmatrix), 128x128, chunk 64 ----------------
#define HP 72
#define SSZ (128 * HP)
#define GEMM_SMEM (4 * SSZ * 2)
#define NIT2 (D_ / 64)

struct GemmAcc { float a[2][8][4]; };

__device__ __forceinline__ void gemm_core(const __half* __restrict__ Xa,
                                          const __half* __restrict__ Wb,
                                          __half* sm, int tid, GemmAcc& acc)
{
    const int wid = tid >> 5, lane = tid & 31;
    const int wm = wid >> 1, wn = wid & 1;
    const int lr = lane & 7, lt = lane >> 3;
    const uint32_t offA = (((lt & 1) * 8 + lr) * HP + (lt >> 1) * 8) * 2;
    const uint32_t offB = (((lt >> 1) * 8 + lr) * HP + (lt & 1) * 8) * 2;

    #pragma unroll
    for (int am = 0; am < 2; am++)
        #pragma unroll
        for (int na = 0; na < 8; na++)
            #pragma unroll
            for (int q = 0; q < 4; q++) acc.a[am][na][q] = 0.f;

    auto load_stage = [&](int ck, int s) {
        __half* As = sm + s * SSZ;
        __half* Bs = sm + 2 * SSZ + s * SSZ;
        #pragma unroll
        for (int i = 0; i < 4; i++) {
            int id = tid + i * 256;
            int r = id >> 3, u = id & 7;
            asm volatile("cp.async.cg.shared.global [%0], [%1], 16;"
                         :: "r"(s2u(As + r * HP + u * 8)),
                            "l"(Xa + (size_t)r * D_ + ck * 64 + u * 8));
            asm volatile("cp.async.cg.shared.global [%0], [%1], 16;"
                         :: "r"(s2u(Bs + r * HP + u * 8)),
                            "l"(Wb + (size_t)r * D_ + ck * 64 + u * 8));
        }
        asm volatile("cp.async.commit_group;");
    };

    load_stage(0, 0);

    for (int it = 0; it < NIT2; it++) {
        if (it + 1 < NIT2) {
            load_stage(it + 1, (it + 1) & 1);
            asm volatile("cp.async.wait_group 1;");
        } else {
            asm volatile("cp.async.wait_group 0;");
        }
        __syncthreads();

        const __half* As = sm + (it & 1) * SSZ;
        const __half* Bs = sm + 2 * SSZ + (it & 1) * SSZ;
        const uint32_t abase = s2u(As) + (uint32_t)(wm * 32 * HP) * 2 + offA;
        const uint32_t bbase = s2u(Bs) + (uint32_t)(wn * 64 * HP) * 2 + offB;

        #pragma unroll
        for (int kk = 0; kk < 4; kk++) {
            uint32_t a[2][4];
            ldm4(a[0][0], a[0][1], a[0][2], a[0][3], abase + kk * 32);
            ldm4(a[1][0], a[1][1], a[1][2], a[1][3], abase + 16 * HP * 2 + kk * 32);
            uint32_t b[8][2];
            #pragma unroll
            for (int j = 0; j < 4; j++) {
                uint32_t r0, r1, r2, r3;
                ldm4(r0, r1, r2, r3, bbase + j * 16 * HP * 2 + kk * 32);
                b[2 * j][0] = r0; b[2 * j][1] = r1;
                b[2 * j + 1][0] = r2; b[2 * j + 1][1] = r3;
            }
            #pragma unroll
            for (int am = 0; am < 2; am++)
                #pragma unroll
                for (int na = 0; na < 8; na++)
                    mma_f16(acc.a[am][na], a[am], b[na]);
        }
        __syncthreads();
    }
}

// Merged Q/K/V projection: grid (8, 64, 3). Writes fp16 head layouts.
__global__ void __launch_bounds__(256, 2)
gemm_proj3()
{
    extern __shared__ __half smh[];
    const int tid = threadIdx.x;
    const int z = blockIdx.z;
    const int m0 = blockIdx.y * 128, n0 = blockIdx.x * 128;

    GemmAcc acc;
    gemm_core(g_xh[z] + (size_t)m0 * D_, g_wh[z] + (size_t)n0 * D_, smh, tid, acc);

    const int wid = tid >> 5, lane = tid & 31;
    const int wm = wid >> 1, wn = wid & 1;
    const int g = lane >> 2, t4 = lane & 3;
    const float scale = (z == 0) ? QSCALE : 1.0f;

    #pragma unroll
    for (int am = 0; am < 2; am++) {
        int r = m0 + wm * 32 + am * 16 + g;
        int b = r >> 11, l = r & 2047;
        #pragma unroll
        for (int na = 0; na < 8; na++) {
            int n = n0 + wn * 64 + na * 8 + 2 * t4;
            int h = n >> 6, hd = n & 63;
            if (z == 2) {
                __half* pv = g_vh + (((size_t)b * H_ + h) * HD_ + hd) * L_ + l;
                pv[0]      = __float2half_rn(acc.a[am][na][0]);
                pv[L_]     = __float2half_rn(acc.a[am][na][1]);
                pv[8]      = __float2half_rn(acc.a[am][na][2]);
                pv[L_ + 8] = __float2half_rn(acc.a[am][na][3]);
            } else {
                __half* Y = (z == 0) ? g_qh : g_kh;
                __half* p0 = Y + (((size_t)b * H_ + h) * L_ + l) * HD_ + hd;
                *(uint32_t*)p0 = pk2(acc.a[am][na][0] * scale, acc.a[am][na][1] * scale);
                __half* p1 = Y + (((size_t)b * H_ + h) * L_ + (l + 8)) * HD_ + hd;
                *(uint32_t*)p1 = pk2(acc.a[am][na][2] * scale, acc.a[am][na][3] * scale);
            }
        }
    }
}

// Output projection: fp16 in (g_ao, g_wh[3]), fp32 out.
__global__ void __launch_bounds__(256, 2)
gemm_out(float* __restrict__ Y)
{
    extern __shared__ __half smh[];
    const int tid = threadIdx.x;
    const int m0 = blockIdx.y * 128, n0 = blockIdx.x * 128;

    GemmAcc acc;
    gemm_core(g_ao + (size_t)m0 * D_, g_wh[3] + (size_t)n0 * D_, smh, tid, acc);

    const int wid = tid >> 5, lane = tid & 31;
    const int wm = wid >> 1, wn = wid & 1;
    const int g = lane >> 2, t4 = lane & 3;

    #pragma unroll
    for (int am = 0; am < 2; am++) {
        int r = m0 + wm * 32 + am * 16 + g;
        #pragma unroll
        for (int na = 0; na < 8; na++) {
            int n = n0 + wn * 64 + na * 8 + 2 * t4;
            float* p0 = Y + (size_t)r * D_ + n;
            p0[0] = acc.a[am][na][0]; p0[1] = acc.a[am][na][1];
            float* p1 = Y + (size_t)(r + 8) * D_ + n;
            p1[0] = acc.a[am][na][2]; p1[1] = acc.a[am][na][3];
        }
    }
}

// ---------------- fp16 flash attention: 8 warps x 16 rows, ldmatrix + log2 softmax ----------------
#define KSTG (2 * 64 * HP)
#define ATTN_SMEM ((128 * HP + 2 * KSTG) * 2)
#define NBLK 296

__global__ void __launch_bounds__(256, 2) attn_mma(__half* __restrict__ ao)
{
    extern __shared__ __half smh[];
    __half* Qs = smh;
    __half* KV = smh + 128 * HP;

    const int tid = threadIdx.x;
    const int wid = tid >> 5, lane = tid & 31;
    const int g = lane >> 2, t4 = lane & 3;
    const int lr = lane & 7, lt = lane >> 3;
    const uint32_t offA = (((lt & 1) * 8 + lr) * HP + (lt >> 1) * 8) * 2;
    const uint32_t offB = (((lt >> 1) * 8 + lr) * HP + (lt & 1) * 8) * 2;
    const int p = blockIdx.x;

    const uint32_t qbase0 = s2u(Qs) + (uint32_t)(wid * 16 * HP) * 2 + offA;

    #pragma unroll 1
    for (int round = 0; round < 4; round++) {
        int rank = (round == 0) ? p
                 : (round == 1) ? (591 - p)
                 : (round == 2) ? (592 + p)
                 : (1183 - p);
        if (rank >= 1024) continue;
        const int qt = 15 - (rank >> 6);
        const int bh = rank & 63;
        const int q0 = qt * 128;

        const __half* Qb = g_qh + ((size_t)bh * L_ + q0) * HD_;
        const __half* Kb = g_kh + (size_t)bh * L_ * HD_;
        const __half* Vb = g_vh + (size_t)bh * HD_ * L_;

        __syncthreads();

        // Q tile: 128 rows x 64 halves = 1024 x 16B chunks (FIXED indexing)
        #pragma unroll
        for (int i = 0; i < 4; i++) {
            int e = tid + i * 256;
            int r = e >> 3, u = e & 7;
            *(uint4*)(Qs + r * HP + u * 8) =
                *(const uint4*)(Qb + (size_t)r * 64 + u * 8);
        }

        auto ldkv = [&](int kt, int st) {
            __half* Ks = KV + st * KSTG;
            __half* Vs = Ks + 64 * HP;
            const __half* kg = Kb + (size_t)kt * 64 * 64;
            const __half* vg = Vb + kt * 64;
            #pragma unroll
            for (int i = 0; i < 2; i++) {
                int e = tid + i * 256;
                int r = e >> 3, u = e & 7;
                asm volatile("cp.async.cg.shared.global [%0], [%1], 16;"
                             :: "r"(s2u(Ks + r * HP + u * 8)),
                                "l"(kg + (size_t)r * 64 + u * 8));
                asm volatile("cp.async.cg.shared.global [%0], [%1], 16;"
                             :: "r"(s2u(Vs + r * HP + u * 8)),
                                "l"(vg + (size_t)r * L_ + u * 8));
            }
            asm volatile("cp.async.commit_group;");
        };

        float mrun[2], lrun[2], O[8][4];
        #pragma unroll
        for (int i = 0; i < 2; i++) { mrun[i] = -1e30f; lrun[i] = 0.f; }
        #pragma unroll
        for (int nt = 0; nt < 8; nt++)
            #pragma unroll
            for (int e = 0; e < 4; e++) O[nt][e] = 0.f;

        const int ntiles = 2 * qt + 2;
        ldkv(0, 0);

        for (int kt = 0; kt < ntiles; kt++) {
            asm volatile("cp.async.wait_group 0;");
            __syncthreads();
            if (kt + 1 < ntiles) ldkv(kt + 1, (kt + 1) & 1);
            const __half* Ks = KV + (kt & 1) * KSTG;
            const __half* Vs = Ks + 64 * HP;
            const uint32_t kbase = s2u(Ks) + offB;
            const uint32_t vbase = s2u(Vs) + offB;

            // ---- S = Q K^T ----
            float S[8][4];
            #pragma unroll
            for (int nt = 0; nt < 8; nt++)
                #pragma unroll
                for (int e = 0; e < 4; e++) S[nt][e] = 0.f;

            #pragma unroll
            for (int kc = 0; kc < 4; kc++) {
                uint32_t af[4];
                ldm4(af[0], af[1], af[2], af[3], qbase0 + kc * 32);
                #pragma unroll
                for (int j = 0; j < 4; j++) {
                    uint32_t r0, r1, r2, r3;
                    ldm4(r0, r1, r2, r3, kbase + j * 16 * HP * 2 + kc * 32);
                    uint32_t bf0[2] = {r0, r1}, bf1[2] = {r2, r3};
                    mma_f16(S[2 * j], af, bf0);
                    mma_f16(S[2 * j + 1], af, bf1);
                }
            }

            // ---- online softmax (log2 domain; mask-specialized) ----
            const bool maskt = (kt >= ntiles - 2);
            uint32_t Ppk[8][2];
            #pragma unroll
            for (int rr = 0; rr < 2; rr++) {
                float mloc = -1e30f;
                if (maskt) {
                    const int rowg = q0 + wid * 16 + rr * 8 + g;
                    #pragma unroll
                    for (int nt = 0; nt < 8; nt++)
                        #pragma unroll
                        for (int e = 0; e < 2; e++) {
                            float vv = S[nt][rr * 2 + e];
                            if ((kt * 64 + nt * 8 + 2 * t4 + e) > rowg) vv = -1e30f;
                            S[nt][rr * 2 + e] = vv;
                            mloc = fmaxf(mloc, vv);
                        }
                } else {
                    #pragma unroll
                    for (int nt = 0; nt < 8; nt++)
                        #pragma unroll
                        for (int e = 0; e < 2; e++)
                            mloc = fmaxf(mloc, S[nt][rr * 2 + e]);
                }
                mloc = fmaxf(mloc, __shfl_xor_sync(0xffffffffu, mloc, 1));
                mloc = fmaxf(mloc, __shfl_xor_sync(0xffffffffu, mloc, 2));
                float mnew = fmaxf(mrun[rr], mloc);
                float corrf = ex2f(mrun[rr] - mnew);
                float sum = 0.f;
                #pragma unroll
                for (int nt = 0; nt < 8; nt++) {
                    float p0 = ex2f(S[nt][rr * 2] - mnew);
                    float p1 = ex2f(S[nt][rr * 2 + 1] - mnew);
                    sum += p0; sum += p1;
                    Ppk[nt][rr] = pk2(p0, p1);
                }
                sum += __shfl_xor_sync(0xffffffffu, sum, 1);
                sum += __shfl_xor_sync(0xffffffffu, sum, 2);
                lrun[rr] = lrun[rr] * corrf + sum;
                mrun[rr] = mnew;
                #pragma unroll
                for (int nt = 0; nt < 8; nt++)
                    #pragma unroll
                    for (int e = 0; e < 2; e++)
                        O[nt][rr * 2 + e] *= corrf;
            }

            // ---- O += P V (packed P is the A-frag; V via ldmatrix) ----
            #pragma unroll
            for (int kc = 0; kc < 4; kc++) {
                uint32_t a[4];
                a[0] = Ppk[2 * kc][0];
                a[1] = Ppk[2 * kc][1];
                a[2] = Ppk[2 * kc + 1][0];
                a[3] = Ppk[2 * kc + 1][1];
                #pragma unroll
                for (int j = 0; j < 4; j++) {
                    uint32_t r0, r1, r2, r3;
                    ldm4(r0, r1, r2, r3, vbase + j * 16 * HP * 2 + kc * 32);
                    uint32_t bf0[2] = {r0, r1}, bf1[2] = {r2, r3};
                    mma_f16(O[2 * j], a, bf0);
                    mma_f16(O[2 * j + 1], a, bf1);
                }
            }
        }

        // ---- epilogue: normalize + fp16 write [b, l, d] ----
        const int b = bh >> 4, h = bh & 15;
        #pragma unroll
        for (int rr = 0; rr < 2; rr++) {
            float inv = 1.f / lrun[rr];
            int row = q0 + wid * 16 + rr * 8 + g;
            __half* op = ao + ((size_t)b * L_ + row) * D_ + h * 64 + 2 * t4;
            #pragma unroll
            for (int nt = 0; nt < 8; nt++)
                *(uint32_t*)(op + nt * 8) =
                    pk2(O[nt][rr * 2] * inv, O[nt][rr * 2 + 1] * inv);
        }
    }
}

// ---------------- launch ----------------
extern "C" void kernel_launch(void* const* d_in, const int* in_sizes, int n_in,
                              void* d_out, int out_size)
{
    const float* q  = (const float*)d_in[0];
    const float* k  = (const float*)d_in[1];
    const float* v  = (const float*)d_in[2];
    // d_in[3] = mask (causal tril) — applied analytically
    const float* Wq = (const float*)d_in[4];
    const float* Wk = (const float*)d_in[5];
    const float* Wv = (const float*)d_in[6];
    const float* Wo = (const float*)d_in[7];
    float* out = (float*)d_out;

    __half* ao;
    cudaGetSymbolAddress((void**)&ao, g_ao);

    cudaFuncSetAttribute(gemm_proj3, cudaFuncAttributeMaxDynamicSharedMemorySize, GEMM_SMEM);
    cudaFuncSetAttribute(gemm_out, cudaFuncAttributeMaxDynamicSharedMemorySize, GEMM_SMEM);
    cudaFuncSetAttribute(attn_mma, cudaFuncAttributeMaxDynamicSharedMemorySize, ATTN_SMEM);

    cvt_x<<<dim3(NX / 8 / 256, 3), 256>>>(q, k, v);
    cvt_w<<<dim3(D_ * D_ / 8 / 256, 4), 256>>>(Wq, Wk, Wv, Wo);
    gemm_proj3<<<dim3(D_ / 128, (B_ * L_) / 128, 3), 256, GEMM_SMEM>>>();
    attn_mma<<<NBLK, 256, ATTN_SMEM>>>(ao);
    gemm_out<<<dim3(D_ / 128, (B_ * L_) / 128), 256, GEMM_SMEM>>>(out);
}

// round 13
// speedup vs baseline: 2.1092x; 1.0040x over previous
#include <cuda_runtime.h>
#include <cuda_fp16.h>
#include <cstdint>
#include <cstddef>

#define B_ 4
#define L_ 2048
#define D_ 1024
#define H_ 16
#define HD_ 64
#define NX (B_*L_*D_)

// Scratch (allocation-free rule: __device__ globals)
__device__ __half g_qh[NX];        // [b,h,l,hd] fp16, pre-scaled 0.125*log2(e)
__device__ __half g_kh[NX];        // [b,h,l,hd] fp16
__device__ __half g_vh[NX];        // [b,h,hd,l] fp16 (TRANSPOSED)
__device__ __half g_ao[NX];        // [b,l,d] fp16
__device__ __half g_xh[3][NX];     // fp16 q,k,v
__device__ __half g_wh[4][D_*D_];  // fp16 Wq,Wk,Wv,Wo

#define QSCALE 0.18033688011112042f   // 0.125 * log2(e)

// ---------------- helpers ----------------
__device__ __forceinline__ uint32_t s2u(const void* p) {
    uint32_t a;
    asm("{ .reg .u64 t; cvta.to.shared.u64 t, %1; cvt.u32.u64 %0, t; }" : "=r"(a) : "l"(p));
    return a;
}
__device__ __forceinline__ uint32_t pk2(float x, float y) {
    __half2 h = __floats2half2_rn(x, y);
    return *(uint32_t*)&h;
}
__device__ __forceinline__ float ex2f(float x) {
    float r; asm("ex2.approx.f32 %0, %1;" : "=f"(r) : "f"(x)); return r;
}
__device__ __forceinline__ void mma_f16(float* c, const uint32_t* a, const uint32_t* b) {
    asm volatile(
        "mma.sync.aligned.m16n8k16.row.col.f32.f16.f16.f32 "
        "{%0,%1,%2,%3}, {%4,%5,%6,%7}, {%8,%9}, {%0,%1,%2,%3};"
        : "+f"(c[0]), "+f"(c[1]), "+f"(c[2]), "+f"(c[3])
        : "r"(a[0]), "r"(a[1]), "r"(a[2]), "r"(a[3]), "r"(b[0]), "r"(b[1]));
}
__device__ __forceinline__ void ldm4(uint32_t& r0, uint32_t& r1, uint32_t& r2,
                                     uint32_t& r3, uint32_t addr) {
    asm volatile("ldmatrix.sync.aligned.m8n8.x4.shared.b16 {%0,%1,%2,%3}, [%4];"
                 : "=r"(r0), "=r"(r1), "=r"(r2), "=r"(r3) : "r"(addr));
}

// ---------------- fp16 convert pass (merged: q,k,v,Wq,Wk,Wv,Wo) ----------------
// Flat work-item space of float8 chunks:
//   [0, 3*NXC)          -> g_xh[z],  z = idx / NXC
//   [3*NXC, 3*NXC+4*WC) -> g_wh[w],  w = (idx - 3*NXC) / WC
#define NXC (NX / 8)
#define WC  (D_ * D_ / 8)
#define CVT_ITEMS (3 * NXC + 4 * WC)

__global__ void __launch_bounds__(256) cvt_all(
        const float* __restrict__ q, const float* __restrict__ k,
        const float* __restrict__ v, const float* __restrict__ wq,
        const float* __restrict__ wk, const float* __restrict__ wv,
        const float* __restrict__ wo)
{
    int idx = blockIdx.x * 256 + threadIdx.x;
    if (idx >= CVT_ITEMS) return;
    const float* src;
    __half* dst;
    if (idx < 3 * NXC) {
        int z = idx / NXC;
        int off = idx - z * NXC;
        src = ((z == 0) ? q : (z == 1) ? k : v) + (size_t)off * 8;
        dst = g_xh[z] + (size_t)off * 8;
    } else {
        int t = idx - 3 * NXC;
        int w = t / WC;
        int off = t - w * WC;
        src = ((w == 0) ? wq : (w == 1) ? wk : (w == 2) ? wv : wo) + (size_t)off * 8;
        dst = g_wh[w] + (size_t)off * 8;
    }
    float4 a = *(const float4*)src;
    float4 b = *(const float4*)(src + 4);
    uint4 o;
    o.x = pk2(a.x, a.y); o.y = pk2(a.z, a.w);
    o.z = pk2(b.x, b.y); o.w = pk2(b.z, b.w);
    *(uint4*)dst = o;
}

// ---------------- fp16 mma.sync GEMM core (ldmatrix), 128x128, chunk 64 ----------------
#define HP 72
#define SSZ (128 * HP)
#define GEMM_SMEM (4 * SSZ * 2)
#define NIT2 (D_ / 64)

struct GemmAcc { float a[2][8][4]; };

__device__ __forceinline__ void gemm_core(const __half* __restrict__ Xa,
                                          const __half* __restrict__ Wb,
                                          __half* sm, int tid, GemmAcc& acc)
{
    const int wid = tid >> 5, lane = tid & 31;
    const int wm = wid >> 1, wn = wid & 1;
    const int lr = lane & 7, lt = lane >> 3;
    const uint32_t offA = (((lt & 1) * 8 + lr) * HP + (lt >> 1) * 8) * 2;
    const uint32_t offB = (((lt >> 1) * 8 + lr) * HP + (lt & 1) * 8) * 2;

    #pragma unroll
    for (int am = 0; am < 2; am++)
        #pragma unroll
        for (int na = 0; na < 8; na++)
            #pragma unroll
            for (int q = 0; q < 4; q++) acc.a[am][na][q] = 0.f;

    auto load_stage = [&](int ck, int s) {
        __half* As = sm + s * SSZ;
        __half* Bs = sm + 2 * SSZ + s * SSZ;
        #pragma unroll
        for (int i = 0; i < 4; i++) {
            int id = tid + i * 256;
            int r = id >> 3, u = id & 7;
            asm volatile("cp.async.cg.shared.global [%0], [%1], 16;"
                         :: "r"(s2u(As + r * HP + u * 8)),
                            "l"(Xa + (size_t)r * D_ + ck * 64 + u * 8));
            asm volatile("cp.async.cg.shared.global [%0], [%1], 16;"
                         :: "r"(s2u(Bs + r * HP + u * 8)),
                            "l"(Wb + (size_t)r * D_ + ck * 64 + u * 8));
        }
        asm volatile("cp.async.commit_group;");
    };

    load_stage(0, 0);

    for (int it = 0; it < NIT2; it++) {
        if (it + 1 < NIT2) {
            load_stage(it + 1, (it + 1) & 1);
            asm volatile("cp.async.wait_group 1;");
        } else {
            asm volatile("cp.async.wait_group 0;");
        }
        __syncthreads();

        const __half* As = sm + (it & 1) * SSZ;
        const __half* Bs = sm + 2 * SSZ + (it & 1) * SSZ;
        const uint32_t abase = s2u(As) + (uint32_t)(wm * 32 * HP) * 2 + offA;
        const uint32_t bbase = s2u(Bs) + (uint32_t)(wn * 64 * HP) * 2 + offB;

        #pragma unroll
        for (int kk = 0; kk < 4; kk++) {
            uint32_t a[2][4];
            ldm4(a[0][0], a[0][1], a[0][2], a[0][3], abase + kk * 32);
            ldm4(a[1][0], a[1][1], a[1][2], a[1][3], abase + 16 * HP * 2 + kk * 32);
            uint32_t b[8][2];
            #pragma unroll
            for (int j = 0; j < 4; j++) {
                uint32_t r0, r1, r2, r3;
                ldm4(r0, r1, r2, r3, bbase + j * 16 * HP * 2 + kk * 32);
                b[2 * j][0] = r0; b[2 * j][1] = r1;
                b[2 * j + 1][0] = r2; b[2 * j + 1][1] = r3;
            }
            #pragma unroll
            for (int am = 0; am < 2; am++)
                #pragma unroll
                for (int na = 0; na < 8; na++)
                    mma_f16(acc.a[am][na], a[am], b[na]);
        }
        __syncthreads();
    }
}

// Merged Q/K/V projection: grid (8, 64, 3). Writes fp16 head layouts.
__global__ void __launch_bounds__(256, 2)
gemm_proj3()
{
    extern __shared__ __half smh[];
    const int tid = threadIdx.x;
    const int z = blockIdx.z;
    const int m0 = blockIdx.y * 128, n0 = blockIdx.x * 128;

    GemmAcc acc;
    gemm_core(g_xh[z] + (size_t)m0 * D_, g_wh[z] + (size_t)n0 * D_, smh, tid, acc);

    const int wid = tid >> 5, lane = tid & 31;
    const int wm = wid >> 1, wn = wid & 1;
    const int g = lane >> 2, t4 = lane & 3;
    const float scale = (z == 0) ? QSCALE : 1.0f;

    #pragma unroll
    for (int am = 0; am < 2; am++) {
        int r = m0 + wm * 32 + am * 16 + g;
        int b = r >> 11, l = r & 2047;
        #pragma unroll
        for (int na = 0; na < 8; na++) {
            int n = n0 + wn * 64 + na * 8 + 2 * t4;
            int h = n >> 6, hd = n & 63;
            if (z == 2) {
                __half* pv = g_vh + (((size_t)b * H_ + h) * HD_ + hd) * L_ + l;
                pv[0]      = __float2half_rn(acc.a[am][na][0]);
                pv[L_]     = __float2half_rn(acc.a[am][na][1]);
                pv[8]      = __float2half_rn(acc.a[am][na][2]);
                pv[L_ + 8] = __float2half_rn(acc.a[am][na][3]);
            } else {
                __half* Y = (z == 0) ? g_qh : g_kh;
                __half* p0 = Y + (((size_t)b * H_ + h) * L_ + l) * HD_ + hd;
                *(uint32_t*)p0 = pk2(acc.a[am][na][0] * scale, acc.a[am][na][1] * scale);
                __half* p1 = Y + (((size_t)b * H_ + h) * L_ + (l + 8)) * HD_ + hd;
                *(uint32_t*)p1 = pk2(acc.a[am][na][2] * scale, acc.a[am][na][3] * scale);
            }
        }
    }
}

// Output projection: fp16 in (g_ao, g_wh[3]), fp32 out.
__global__ void __launch_bounds__(256, 2)
gemm_out(float* __restrict__ Y)
{
    extern __shared__ __half smh[];
    const int tid = threadIdx.x;
    const int m0 = blockIdx.y * 128, n0 = blockIdx.x * 128;

    GemmAcc acc;
    gemm_core(g_ao + (size_t)m0 * D_, g_wh[3] + (size_t)n0 * D_, smh, tid, acc);

    const int wid = tid >> 5, lane = tid & 31;
    const int wm = wid >> 1, wn = wid & 1;
    const int g = lane >> 2, t4 = lane & 3;

    #pragma unroll
    for (int am = 0; am < 2; am++) {
        int r = m0 + wm * 32 + am * 16 + g;
        #pragma unroll
        for (int na = 0; na < 8; na++) {
            int n = n0 + wn * 64 + na * 8 + 2 * t4;
            float* p0 = Y + (size_t)r * D_ + n;
            p0[0] = acc.a[am][na][0]; p0[1] = acc.a[am][na][1];
            float* p1 = Y + (size_t)(r + 8) * D_ + n;
            p1[0] = acc.a[am][na][2]; p1[1] = acc.a[am][na][3];
        }
    }
}

// ---------------- fp16 flash attention: 8 warps x 16 rows, masked-tile skip ----------------
#define KSTG (2 * 64 * HP)
#define ATTN_SMEM ((128 * HP + 2 * KSTG) * 2)
#define NBLK 296

__global__ void __launch_bounds__(256, 2) attn_mma(__half* __restrict__ ao)
{
    extern __shared__ __half smh[];
    __half* Qs = smh;
    __half* KV = smh + 128 * HP;

    const int tid = threadIdx.x;
    const int wid = tid >> 5, lane = tid & 31;
    const int g = lane >> 2, t4 = lane & 3;
    const int lr = lane & 7, lt = lane >> 3;
    const uint32_t offA = (((lt & 1) * 8 + lr) * HP + (lt >> 1) * 8) * 2;
    const uint32_t offB = (((lt >> 1) * 8 + lr) * HP + (lt & 1) * 8) * 2;
    const int p = blockIdx.x;

    const uint32_t qbase0 = s2u(Qs) + (uint32_t)(wid * 16 * HP) * 2 + offA;

    #pragma unroll 1
    for (int round = 0; round < 4; round++) {
        int rank = (round == 0) ? p
                 : (round == 1) ? (591 - p)
                 : (round == 2) ? (592 + p)
                 : (1183 - p);
        if (rank >= 1024) continue;
        const int qt = 15 - (rank >> 6);
        const int bh = rank & 63;
        const int q0 = qt * 128;

        const __half* Qb = g_qh + ((size_t)bh * L_ + q0) * HD_;
        const __half* Kb = g_kh + (size_t)bh * L_ * HD_;
        const __half* Vb = g_vh + (size_t)bh * HD_ * L_;

        __syncthreads();

        // Q tile: 128 rows x 64 halves = 1024 x 16B chunks
        #pragma unroll
        for (int i = 0; i < 4; i++) {
            int e = tid + i * 256;
            int r = e >> 3, u = e & 7;
            *(uint4*)(Qs + r * HP + u * 8) =
                *(const uint4*)(Qb + (size_t)r * 64 + u * 8);
        }

        auto ldkv = [&](int kt, int st) {
            __half* Ks = KV + st * KSTG;
            __half* Vs = Ks + 64 * HP;
            const __half* kg = Kb + (size_t)kt * 64 * 64;
            const __half* vg = Vb + kt * 64;
            #pragma unroll
            for (int i = 0; i < 2; i++) {
                int e = tid + i * 256;
                int r = e >> 3, u = e & 7;
                asm volatile("cp.async.cg.shared.global [%0], [%1], 16;"
                             :: "r"(s2u(Ks + r * HP + u * 8)),
                                "l"(kg + (size_t)r * 64 + u * 8));
                asm volatile("cp.async.cg.shared.global [%0], [%1], 16;"
                             :: "r"(s2u(Vs + r * HP + u * 8)),
                                "l"(vg + (size_t)r * L_ + u * 8));
            }
            asm volatile("cp.async.commit_group;");
        };

        float mrun[2], lrun[2], O[8][4];
        #pragma unroll
        for (int i = 0; i < 2; i++) { mrun[i] = -1e30f; lrun[i] = 0.f; }
        #pragma unroll
        for (int nt = 0; nt < 8; nt++)
            #pragma unroll
            for (int e = 0; e < 4; e++) O[nt][e] = 0.f;

        const int ntiles = 2 * qt + 2;
        // Warp-level tile count: warps 0-3 (rows q0..q0+63) have a FULLY masked
        // final tile (all P = 0 exactly) -> skip its compute; bit-identical.
        const int ntw = 2 * qt + 1 + (wid >= 4 ? 1 : 0);
        ldkv(0, 0);

        for (int kt = 0; kt < ntiles; kt++) {
            asm volatile("cp.async.wait_group 0;");
            __syncthreads();
            if (kt + 1 < ntiles) ldkv(kt + 1, (kt + 1) & 1);
            if (kt < ntw) {
                const __half* Ks = KV + (kt & 1) * KSTG;
                const __half* Vs = Ks + 64 * HP;
                const uint32_t kbase = s2u(Ks) + offB;
                const uint32_t vbase = s2u(Vs) + offB;

                // ---- S = Q K^T ----
                float S[8][4];
                #pragma unroll
                for (int nt = 0; nt < 8; nt++)
                    #pragma unroll
                    for (int e = 0; e < 4; e++) S[nt][e] = 0.f;

                #pragma unroll
                for (int kc = 0; kc < 4; kc++) {
                    uint32_t af[4];
                    ldm4(af[0], af[1], af[2], af[3], qbase0 + kc * 32);
                    #pragma unroll
                    for (int j = 0; j < 4; j++) {
                        uint32_t r0, r1, r2, r3;
                        ldm4(r0, r1, r2, r3, kbase + j * 16 * HP * 2 + kc * 32);
                        uint32_t bf0[2] = {r0, r1}, bf1[2] = {r2, r3};
                        mma_f16(S[2 * j], af, bf0);
                        mma_f16(S[2 * j + 1], af, bf1);
                    }
                }

                // ---- online softmax (log2 domain; masked only on warp's last tile) ----
                const bool maskt = (kt == ntw - 1);
                uint32_t Ppk[8][2];
                #pragma unroll
                for (int rr = 0; rr < 2; rr++) {
                    float mloc = -1e30f;
                    if (maskt) {
                        const int rowg = q0 + wid * 16 + rr * 8 + g;
                        #pragma unroll
                        for (int nt = 0; nt < 8; nt++)
                            #pragma unroll
                            for (int e = 0; e < 2; e++) {
                                float vv = S[nt][rr * 2 + e];
                                if ((kt * 64 + nt * 8 + 2 * t4 + e) > rowg) vv = -1e30f;
                                S[nt][rr * 2 + e] = vv;
                                mloc = fmaxf(mloc, vv);
                            }
                    } else {
                        #pragma unroll
                        for (int nt = 0; nt < 8; nt++)
                            #pragma unroll
                            for (int e = 0; e < 2; e++)
                                mloc = fmaxf(mloc, S[nt][rr * 2 + e]);
                    }
                    mloc = fmaxf(mloc, __shfl_xor_sync(0xffffffffu, mloc, 1));
                    mloc = fmaxf(mloc, __shfl_xor_sync(0xffffffffu, mloc, 2));
                    float mnew = fmaxf(mrun[rr], mloc);
                    float corrf = ex2f(mrun[rr] - mnew);
                    float sum = 0.f;
                    #pragma unroll
                    for (int nt = 0; nt < 8; nt++) {
                        float p0 = ex2f(S[nt][rr * 2] - mnew);
                        float p1 = ex2f(S[nt][rr * 2 + 1] - mnew);
                        sum += p0; sum += p1;
                        Ppk[nt][rr] = pk2(p0, p1);
                    }
                    sum += __shfl_xor_sync(0xffffffffu, sum, 1);
                    sum += __shfl_xor_sync(0xffffffffu, sum, 2);
                    lrun[rr] = lrun[rr] * corrf + sum;
                    mrun[rr] = mnew;
                    #pragma unroll
                    for (int nt = 0; nt < 8; nt++)
                        #pragma unroll
                        for (int e = 0; e < 2; e++)
                            O[nt][rr * 2 + e] *= corrf;
                }

                // ---- O += P V ----
                #pragma unroll
                for (int kc = 0; kc < 4; kc++) {
                    uint32_t a[4];
                    a[0] = Ppk[2 * kc][0];
                    a[1] = Ppk[2 * kc][1];
                    a[2] = Ppk[2 * kc + 1][0];
                    a[3] = Ppk[2 * kc + 1][1];
                    #pragma unroll
                    for (int j = 0; j < 4; j++) {
                        uint32_t r0, r1, r2, r3;
                        ldm4(r0, r1, r2, r3, vbase + j * 16 * HP * 2 + kc * 32);
                        uint32_t bf0[2] = {r0, r1}, bf1[2] = {r2, r3};
                        mma_f16(O[2 * j], a, bf0);
                        mma_f16(O[2 * j + 1], a, bf1);
                    }
                }
            }
        }

        // ---- epilogue: normalize + fp16 write [b, l, d] ----
        const int b = bh >> 4, h = bh & 15;
        #pragma unroll
        for (int rr = 0; rr < 2; rr++) {
            float inv = 1.f / lrun[rr];
            int row = q0 + wid * 16 + rr * 8 + g;
            __half* op = ao + ((size_t)b * L_ + row) * D_ + h * 64 + 2 * t4;
            #pragma unroll
            for (int nt = 0; nt < 8; nt++)
                *(uint32_t*)(op + nt * 8) =
                    pk2(O[nt][rr * 2] * inv, O[nt][rr * 2 + 1] * inv);
        }
    }
}

// ---------------- launch ----------------
extern "C" void kernel_launch(void* const* d_in, const int* in_sizes, int n_in,
                              void* d_out, int out_size)
{
    const float* q  = (const float*)d_in[0];
    const float* k  = (const float*)d_in[1];
    const float* v  = (const float*)d_in[2];
    // d_in[3] = mask (causal tril) — applied analytically
    const float* Wq = (const float*)d_in[4];
    const float* Wk = (const float*)d_in[5];
    const float* Wv = (const float*)d_in[6];
    const float* Wo = (const float*)d_in[7];
    float* out = (float*)d_out;

    __half* ao;
    cudaGetSymbolAddress((void**)&ao, g_ao);

    cudaFuncSetAttribute(gemm_proj3, cudaFuncAttributeMaxDynamicSharedMemorySize, GEMM_SMEM);
    cudaFuncSetAttribute(gemm_out, cudaFuncAttributeMaxDynamicSharedMemorySize, GEMM_SMEM);
    cudaFuncSetAttribute(attn_mma, cudaFuncAttributeMaxDynamicSharedMemorySize, ATTN_SMEM);

    cvt_all<<<(CVT_ITEMS + 255) / 256, 256>>>(q, k, v, Wq, Wk, Wv, Wo);
    gemm_proj3<<<dim3(D_ / 128, (B_ * L_) / 128, 3), 256, GEMM_SMEM>>>();
    attn_mma<<<NBLK, 256, ATTN_SMEM>>>(ao);
    gemm_out<<<dim3(D_ / 128, (B_ * L_) / 128), 256, GEMM_SMEM>>>(out);
}

// round 14
// speedup vs baseline: 2.1311x; 1.0104x over previous
#include <cuda_runtime.h>
#include <cuda_fp16.h>
#include <cstdint>
#include <cstddef>

#define B_ 4
#define L_ 2048
#define D_ 1024
#define H_ 16
#define HD_ 64
#define NX (B_*L_*D_)

// Scratch (allocation-free rule: __device__ globals)
__device__ __half g_qh[NX];        // [b,h,l,hd] fp16, pre-scaled 0.125*log2(e)
__device__ __half g_kh[NX];        // [b,h,l,hd] fp16
__device__ __half g_vh[NX];        // [b,h,hd,l] fp16 (TRANSPOSED)
__device__ __half g_ao[NX];        // [b,l,d] fp16
__device__ __half g_xh[3][NX];     // fp16 q,k,v
__device__ __half g_wh[4][D_*D_];  // fp16 Wq,Wk,Wv,Wo

#define QSCALE 0.18033688011112042f   // 0.125 * log2(e)

// ---------------- helpers ----------------
__device__ __forceinline__ uint32_t s2u(const void* p) {
    uint32_t a;
    asm("{ .reg .u64 t; cvta.to.shared.u64 t, %1; cvt.u32.u64 %0, t; }" : "=r"(a) : "l"(p));
    return a;
}
__device__ __forceinline__ uint32_t pk2(float x, float y) {
    __half2 h = __floats2half2_rn(x, y);
    return *(uint32_t*)&h;
}
__device__ __forceinline__ float ex2f(float x) {
    float r; asm("ex2.approx.f32 %0, %1;" : "=f"(r) : "f"(x)); return r;
}
__device__ __forceinline__ void mma_f16(float* c, const uint32_t* a, const uint32_t* b) {
    asm volatile(
        "mma.sync.aligned.m16n8k16.row.col.f32.f16.f16.f32 "
        "{%0,%1,%2,%3}, {%4,%5,%6,%7}, {%8,%9}, {%0,%1,%2,%3};"
        : "+f"(c[0]), "+f"(c[1]), "+f"(c[2]), "+f"(c[3])
        : "r"(a[0]), "r"(a[1]), "r"(a[2]), "r"(a[3]), "r"(b[0]), "r"(b[1]));
}
__device__ __forceinline__ void ldm4(uint32_t& r0, uint32_t& r1, uint32_t& r2,
                                     uint32_t& r3, uint32_t addr) {
    asm volatile("ldmatrix.sync.aligned.m8n8.x4.shared.b16 {%0,%1,%2,%3}, [%4];"
                 : "=r"(r0), "=r"(r1), "=r"(r2), "=r"(r3) : "r"(addr));
}

// ---------------- fp16 convert pass (merged: q,k,v,Wq,Wk,Wv,Wo) ----------------
#define NXC (NX / 8)
#define WC  (D_ * D_ / 8)
#define CVT_ITEMS (3 * NXC + 4 * WC)

__global__ void __launch_bounds__(256) cvt_all(
        const float* __restrict__ q, const float* __restrict__ k,
        const float* __restrict__ v, const float* __restrict__ wq,
        const float* __restrict__ wk, const float* __restrict__ wv,
        const float* __restrict__ wo)
{
    int idx = blockIdx.x * 256 + threadIdx.x;
    if (idx >= CVT_ITEMS) return;
    const float* src;
    __half* dst;
    if (idx < 3 * NXC) {
        int z = idx / NXC;
        int off = idx - z * NXC;
        src = ((z == 0) ? q : (z == 1) ? k : v) + (size_t)off * 8;
        dst = g_xh[z] + (size_t)off * 8;
    } else {
        int t = idx - 3 * NXC;
        int w = t / WC;
        int off = t - w * WC;
        src = ((w == 0) ? wq : (w == 1) ? wk : (w == 2) ? wv : wo) + (size_t)off * 8;
        dst = g_wh[w] + (size_t)off * 8;
    }
    float4 a = *(const float4*)src;
    float4 b = *(const float4*)(src + 4);
    uint4 o;
    o.x = pk2(a.x, a.y); o.y = pk2(a.z, a.w);
    o.z = pk2(b.x, b.y); o.w = pk2(b.z, b.w);
    *(uint4*)dst = o;
}

// ---------------- fp16 mma.sync GEMM core: 3-stage pipeline, 1 barrier/iter ----------------
#define HP 72
#define SSZ (128 * HP)          // one operand, one stage (halves)
#define STG (2 * SSZ)           // A+B, one stage (halves)
#define GEMM_SMEM (3 * STG * 2) // 110592 bytes
#define NIT2 (D_ / 64)

struct GemmAcc { float a[2][8][4]; };

__device__ __forceinline__ void gemm_core(const __half* __restrict__ Xa,
                                          const __half* __restrict__ Wb,
                                          __half* sm, int tid, GemmAcc& acc)
{
    const int wid = tid >> 5, lane = tid & 31;
    const int wm = wid >> 1, wn = wid & 1;
    const int lr = lane & 7, lt = lane >> 3;
    const uint32_t offA = (((lt & 1) * 8 + lr) * HP + (lt >> 1) * 8) * 2;
    const uint32_t offB = (((lt >> 1) * 8 + lr) * HP + (lt & 1) * 8) * 2;

    #pragma unroll
    for (int am = 0; am < 2; am++)
        #pragma unroll
        for (int na = 0; na < 8; na++)
            #pragma unroll
            for (int q = 0; q < 4; q++) acc.a[am][na][q] = 0.f;

    auto load_stage = [&](int ck, int s) {
        __half* As = sm + s * STG;
        __half* Bs = As + SSZ;
        #pragma unroll
        for (int i = 0; i < 4; i++) {
            int id = tid + i * 256;
            int r = id >> 3, u = id & 7;
            asm volatile("cp.async.cg.shared.global [%0], [%1], 16;"
                         :: "r"(s2u(As + r * HP + u * 8)),
                            "l"(Xa + (size_t)r * D_ + ck * 64 + u * 8));
            asm volatile("cp.async.cg.shared.global [%0], [%1], 16;"
                         :: "r"(s2u(Bs + r * HP + u * 8)),
                            "l"(Wb + (size_t)r * D_ + ck * 64 + u * 8));
        }
        asm volatile("cp.async.commit_group;");
    };

    load_stage(0, 0);
    load_stage(1, 1);

    for (int it = 0; it < NIT2; it++) {
        // stage `it` ready: one group per iter committed; allow 1 newest pending
        asm volatile("cp.async.wait_group 1;");
        __syncthreads();   // visibility for stage it; readers of stage (it+2)%3 done
        if (it + 2 < NIT2) {
            load_stage(it + 2, (it + 2) % 3);
        } else {
            asm volatile("cp.async.commit_group;");   // uniform group count
        }

        const __half* As = sm + (it % 3) * STG;
        const __half* Bs = As + SSZ;
        const uint32_t abase = s2u(As) + (uint32_t)(wm * 32 * HP) * 2 + offA;
        const uint32_t bbase = s2u(Bs) + (uint32_t)(wn * 64 * HP) * 2 + offB;

        #pragma unroll
        for (int kk = 0; kk < 4; kk++) {
            uint32_t a[2][4];
            ldm4(a[0][0], a[0][1], a[0][2], a[0][3], abase + kk * 32);
            ldm4(a[1][0], a[1][1], a[1][2], a[1][3], abase + 16 * HP * 2 + kk * 32);
            uint32_t b[8][2];
            #pragma unroll
            for (int j = 0; j < 4; j++) {
                uint32_t r0, r1, r2, r3;
                ldm4(r0, r1, r2, r3, bbase + j * 16 * HP * 2 + kk * 32);
                b[2 * j][0] = r0; b[2 * j][1] = r1;
                b[2 * j + 1][0] = r2; b[2 * j + 1][1] = r3;
            }
            #pragma unroll
            for (int am = 0; am < 2; am++)
                #pragma unroll
                for (int na = 0; na < 8; na++)
                    mma_f16(acc.a[am][na], a[am], b[na]);
        }
    }
    __syncthreads();   // protect smem before caller reuses / next tile
}

// Merged Q/K/V projection: grid (8, 64, 3). Writes fp16 head layouts.
__global__ void __launch_bounds__(256, 2)
gemm_proj3()
{
    extern __shared__ __half smh[];
    const int tid = threadIdx.x;
    const int z = blockIdx.z;
    const int m0 = blockIdx.y * 128, n0 = blockIdx.x * 128;

    GemmAcc acc;
    gemm_core(g_xh[z] + (size_t)m0 * D_, g_wh[z] + (size_t)n0 * D_, smh, tid, acc);

    const int wid = tid >> 5, lane = tid & 31;
    const int wm = wid >> 1, wn = wid & 1;
    const int g = lane >> 2, t4 = lane & 3;
    const float scale = (z == 0) ? QSCALE : 1.0f;

    #pragma unroll
    for (int am = 0; am < 2; am++) {
        int r = m0 + wm * 32 + am * 16 + g;
        int b = r >> 11, l = r & 2047;
        #pragma unroll
        for (int na = 0; na < 8; na++) {
            int n = n0 + wn * 64 + na * 8 + 2 * t4;
            int h = n >> 6, hd = n & 63;
            if (z == 2) {
                __half* pv = g_vh + (((size_t)b * H_ + h) * HD_ + hd) * L_ + l;
                pv[0]      = __float2half_rn(acc.a[am][na][0]);
                pv[L_]     = __float2half_rn(acc.a[am][na][1]);
                pv[8]      = __float2half_rn(acc.a[am][na][2]);
                pv[L_ + 8] = __float2half_rn(acc.a[am][na][3]);
            } else {
                __half* Y = (z == 0) ? g_qh : g_kh;
                __half* p0 = Y + (((size_t)b * H_ + h) * L_ + l) * HD_ + hd;
                *(uint32_t*)p0 = pk2(acc.a[am][na][0] * scale, acc.a[am][na][1] * scale);
                __half* p1 = Y + (((size_t)b * H_ + h) * L_ + (l + 8)) * HD_ + hd;
                *(uint32_t*)p1 = pk2(acc.a[am][na][2] * scale, acc.a[am][na][3] * scale);
            }
        }
    }
}

// Output projection: fp16 in (g_ao, g_wh[3]), fp32 out.
__global__ void __launch_bounds__(256, 2)
gemm_out(float* __restrict__ Y)
{
    extern __shared__ __half smh[];
    const int tid = threadIdx.x;
    const int m0 = blockIdx.y * 128, n0 = blockIdx.x * 128;

    GemmAcc acc;
    gemm_core(g_ao + (size_t)m0 * D_, g_wh[3] + (size_t)n0 * D_, smh, tid, acc);

    const int wid = tid >> 5, lane = tid & 31;
    const int wm = wid >> 1, wn = wid & 1;
    const int g = lane >> 2, t4 = lane & 3;

    #pragma unroll
    for (int am = 0; am < 2; am++) {
        int r = m0 + wm * 32 + am * 16 + g;
        #pragma unroll
        for (int na = 0; na < 8; na++) {
            int n = n0 + wn * 64 + na * 8 + 2 * t4;
            float* p0 = Y + (size_t)r * D_ + n;
            p0[0] = acc.a[am][na][0]; p0[1] = acc.a[am][na][1];
            float* p1 = Y + (size_t)(r + 8) * D_ + n;
            p1[0] = acc.a[am][na][2]; p1[1] = acc.a[am][na][3];
        }
    }
}

// ---------------- fp16 flash attention: 8 warps x 16 rows, masked-tile skip ----------------
#define KSTG (2 * 64 * HP)
#define ATTN_SMEM ((128 * HP + 2 * KSTG) * 2)
#define NBLK 296

__global__ void __launch_bounds__(256, 2) attn_mma(__half* __restrict__ ao)
{
    extern __shared__ __half smh[];
    __half* Qs = smh;
    __half* KV = smh + 128 * HP;

    const int tid = threadIdx.x;
    const int wid = tid >> 5, lane = tid & 31;
    const int g = lane >> 2, t4 = lane & 3;
    const int lr = lane & 7, lt = lane >> 3;
    const uint32_t offA = (((lt & 1) * 8 + lr) * HP + (lt >> 1) * 8) * 2;
    const uint32_t offB = (((lt >> 1) * 8 + lr) * HP + (lt & 1) * 8) * 2;
    const int p = blockIdx.x;

    const uint32_t qbase0 = s2u(Qs) + (uint32_t)(wid * 16 * HP) * 2 + offA;

    #pragma unroll 1
    for (int round = 0; round < 4; round++) {
        int rank = (round == 0) ? p
                 : (round == 1) ? (591 - p)
                 : (round == 2) ? (592 + p)
                 : (1183 - p);
        if (rank >= 1024) continue;
        const int qt = 15 - (rank >> 6);
        const int bh = rank & 63;
        const int q0 = qt * 128;

        const __half* Qb = g_qh + ((size_t)bh * L_ + q0) * HD_;
        const __half* Kb = g_kh + (size_t)bh * L_ * HD_;
        const __half* Vb = g_vh + (size_t)bh * HD_ * L_;

        __syncthreads();

        #pragma unroll
        for (int i = 0; i < 4; i++) {
            int e = tid + i * 256;
            int r = e >> 3, u = e & 7;
            *(uint4*)(Qs + r * HP + u * 8) =
                *(const uint4*)(Qb + (size_t)r * 64 + u * 8);
        }

        auto ldkv = [&](int kt, int st) {
            __half* Ks = KV + st * KSTG;
            __half* Vs = Ks + 64 * HP;
            const __half* kg = Kb + (size_t)kt * 64 * 64;
            const __half* vg = Vb + kt * 64;
            #pragma unroll
            for (int i = 0; i < 2; i++) {
                int e = tid + i * 256;
                int r = e >> 3, u = e & 7;
                asm volatile("cp.async.cg.shared.global [%0], [%1], 16;"
                             :: "r"(s2u(Ks + r * HP + u * 8)),
                                "l"(kg + (size_t)r * 64 + u * 8));
                asm volatile("cp.async.cg.shared.global [%0], [%1], 16;"
                             :: "r"(s2u(Vs + r * HP + u * 8)),
                                "l"(vg + (size_t)r * L_ + u * 8));
            }
            asm volatile("cp.async.commit_group;");
        };

        float mrun[2], lrun[2], O[8][4];
        #pragma unroll
        for (int i = 0; i < 2; i++) { mrun[i] = -1e30f; lrun[i] = 0.f; }
        #pragma unroll
        for (int nt = 0; nt < 8; nt++)
            #pragma unroll
            for (int e = 0; e < 4; e++) O[nt][e] = 0.f;

        const int ntiles = 2 * qt + 2;
        const int ntw = 2 * qt + 1 + (wid >= 4 ? 1 : 0);
        ldkv(0, 0);

        for (int kt = 0; kt < ntiles; kt++) {
            asm volatile("cp.async.wait_group 0;");
            __syncthreads();
            if (kt + 1 < ntiles) ldkv(kt + 1, (kt + 1) & 1);
            if (kt < ntw) {
                const __half* Ks = KV + (kt & 1) * KSTG;
                const __half* Vs = Ks + 64 * HP;
                const uint32_t kbase = s2u(Ks) + offB;
                const uint32_t vbase = s2u(Vs) + offB;

                float S[8][4];
                #pragma unroll
                for (int nt = 0; nt < 8; nt++)
                    #pragma unroll
                    for (int e = 0; e < 4; e++) S[nt][e] = 0.f;

                #pragma unroll
                for (int kc = 0; kc < 4; kc++) {
                    uint32_t af[4];
                    ldm4(af[0], af[1], af[2], af[3], qbase0 + kc * 32);
                    #pragma unroll
                    for (int j = 0; j < 4; j++) {
                        uint32_t r0, r1, r2, r3;
                        ldm4(r0, r1, r2, r3, kbase + j * 16 * HP * 2 + kc * 32);
                        uint32_t bf0[2] = {r0, r1}, bf1[2] = {r2, r3};
                        mma_f16(S[2 * j], af, bf0);
                        mma_f16(S[2 * j + 1], af, bf1);
                    }
                }

                const bool maskt = (kt == ntw - 1);
                uint32_t Ppk[8][2];
                #pragma unroll
                for (int rr = 0; rr < 2; rr++) {
                    float mloc = -1e30f;
                    if (maskt) {
                        const int rowg = q0 + wid * 16 + rr * 8 + g;
                        #pragma unroll
                        for (int nt = 0; nt < 8; nt++)
                            #pragma unroll
                            for (int e = 0; e < 2; e++) {
                                float vv = S[nt][rr * 2 + e];
                                if ((kt * 64 + nt * 8 + 2 * t4 + e) > rowg) vv = -1e30f;
                                S[nt][rr * 2 + e] = vv;
                                mloc = fmaxf(mloc, vv);
                            }
                    } else {
                        #pragma unroll
                        for (int nt = 0; nt < 8; nt++)
                            #pragma unroll
                            for (int e = 0; e < 2; e++)
                                mloc = fmaxf(mloc, S[nt][rr * 2 + e]);
                    }
                    mloc = fmaxf(mloc, __shfl_xor_sync(0xffffffffu, mloc, 1));
                    mloc = fmaxf(mloc, __shfl_xor_sync(0xffffffffu, mloc, 2));
                    float mnew = fmaxf(mrun[rr], mloc);
                    float corrf = ex2f(mrun[rr] - mnew);
                    float sum = 0.f;
                    #pragma unroll
                    for (int nt = 0; nt < 8; nt++) {
                        float p0 = ex2f(S[nt][rr * 2] - mnew);
                        float p1 = ex2f(S[nt][rr * 2 + 1] - mnew);
                        sum += p0; sum += p1;
                        Ppk[nt][rr] = pk2(p0, p1);
                    }
                    sum += __shfl_xor_sync(0xffffffffu, sum, 1);
                    sum += __shfl_xor_sync(0xffffffffu, sum, 2);
                    lrun[rr] = lrun[rr] * corrf + sum;
                    mrun[rr] = mnew;
                    #pragma unroll
                    for (int nt = 0; nt < 8; nt++)
                        #pragma unroll
                        for (int e = 0; e < 2; e++)
                            O[nt][rr * 2 + e] *= corrf;
                }

                #pragma unroll
                for (int kc = 0; kc < 4; kc++) {
                    uint32_t a[4];
                    a[0] = Ppk[2 * kc][0];
                    a[1] = Ppk[2 * kc][1];
                    a[2] = Ppk[2 * kc + 1][0];
                    a[3] = Ppk[2 * kc + 1][1];
                    #pragma unroll
                    for (int j = 0; j < 4; j++) {
                        uint32_t r0, r1, r2, r3;
                        ldm4(r0, r1, r2, r3, vbase + j * 16 * HP * 2 + kc * 32);
                        uint32_t bf0[2] = {r0, r1}, bf1[2] = {r2, r3};
                        mma_f16(O[2 * j], a, bf0);
                        mma_f16(O[2 * j + 1], a, bf1);
                    }
                }
            }
        }

        // ---- epilogue: normalize + fp16 write [b, l, d] ----
        const int b = bh >> 4, h = bh & 15;
        #pragma unroll
        for (int rr = 0; rr < 2; rr++) {
            float inv = 1.f / lrun[rr];
            int row = q0 + wid * 16 + rr * 8 + g;
            __half* op = ao + ((size_t)b * L_ + row) * D_ + h * 64 + 2 * t4;
            #pragma unroll
            for (int nt = 0; nt < 8; nt++)
                *(uint32_t*)(op + nt * 8) =
                    pk2(O[nt][rr * 2] * inv, O[nt][rr * 2 + 1] * inv);
        }
    }
}

// ---------------- launch ----------------
extern "C" void kernel_launch(void* const* d_in, const int* in_sizes, int n_in,
                              void* d_out, int out_size)
{
    const float* q  = (const float*)d_in[0];
    const float* k  = (const float*)d_in[1];
    const float* v  = (const float*)d_in[2];
    // d_in[3] = mask (causal tril) — applied analytically
    const float* Wq = (const float*)d_in[4];
    const float* Wk = (const float*)d_in[5];
    const float* Wv = (const float*)d_in[6];
    const float* Wo = (const float*)d_in[7];
    float* out = (float*)d_out;

    __half* ao;
    cudaGetSymbolAddress((void**)&ao, g_ao);

    cudaFuncSetAttribute(gemm_proj3, cudaFuncAttributeMaxDynamicSharedMemorySize, GEMM_SMEM);
    cudaFuncSetAttribute(gemm_out, cudaFuncAttributeMaxDynamicSharedMemorySize, GEMM_SMEM);
    cudaFuncSetAttribute(attn_mma, cudaFuncAttributeMaxDynamicSharedMemorySize, ATTN_SMEM);

    cvt_all<<<(CVT_ITEMS + 255) / 256, 256>>>(q, k, v, Wq, Wk, Wv, Wo);
    gemm_proj3<<<dim3(D_ / 128, (B_ * L_) / 128, 3), 256, GEMM_SMEM>>>();
    attn_mma<<<NBLK, 256, ATTN_SMEM>>>(ao);
    gemm_out<<<dim3(D_ / 128, (B_ * L_) / 128), 256, GEMM_SMEM>>>(out);
}